// round 1
// baseline (speedup 1.0000x reference)
#include <cuda_runtime.h>
#include <cuda_bf16.h>
#include <math.h>

// ---------------- problem constants ----------------
#define Bb 4
#define NTOK 5440
#define Mrows (Bb * NTOK)   // 21760
#define Dd 256
#define FFd 1024
#define NHh 8
#define NLl 4
#define NPp 4
#define DHh 32

// level shapes (square): (64,64),(32,32),(16,16),(8,8)
__device__ __constant__ int c_lvl_W[4]     = {64, 32, 16, 8};
__device__ __constant__ int c_lvl_start[4] = {0, 4096, 5120, 5376};

// ---------------- scratch (device globals; no allocs allowed) ----------------
__device__ float g_q    [Mrows * Dd];     // src + pos
__device__ float g_value[Mrows * Dd];     // src @ Wv^T + b (masked)
__device__ float g_off  [Mrows * Dd];     // sampling offsets (256 per token)
__device__ float g_attn [Mrows * 128];    // attention weights after softmax
__device__ float g_a    [Mrows * Dd];     // msdeform output
__device__ float g_t1   [Mrows * Dd];     // pre-LN1 (src + attn-out)
__device__ float g_x    [Mrows * Dd];     // LN1 output
__device__ float g_h    [Mrows * FFd];    // FFN hidden
__device__ float g_t2   [Mrows * Dd];     // pre-LN2 (x + ffn-out)

// ---------------- elementwise: q = src + pos ----------------
__global__ void add_kernel(const float* __restrict__ a, const float* __restrict__ b,
                           float* __restrict__ o) {
    int i = blockIdx.x * blockDim.x + threadIdx.x;
    float4 va = ((const float4*)a)[i];
    float4 vb = ((const float4*)b)[i];
    float4 vo = make_float4(va.x + vb.x, va.y + vb.y, va.z + vb.z, va.w + vb.w);
    ((float4*)o)[i] = vo;
}

// ---------------- SGEMM: C[M,N] = A[M,K] @ W[N,K]^T + bias, fused epilogue ----------------
// BM=128, BN=128, BK=16, 256 threads, 8x8 per-thread micro-tile.
// M % 128 == 0, N % 128 == 0, K % 16 == 0 required (true for all our shapes).
#define BM 128
#define BN 128
#define BK 16
#define SLD 132   // padded smem leading dim (conflict-free)

enum { E_NONE = 0, E_MASK = 1, E_RELU = 2, E_ADD = 3 };

template <int EPI>
__global__ __launch_bounds__(256, 2)
void sgemm_kernel(const float* __restrict__ A, const float* __restrict__ W,
                  const float* __restrict__ bias, float* __restrict__ C,
                  int M, int N, int K,
                  const float* __restrict__ add, const unsigned char* __restrict__ mask) {
    __shared__ float As[BK][SLD];
    __shared__ float Bs[BK][SLD];

    const int bm = blockIdx.y * BM;
    const int bn = blockIdx.x * BN;
    const int tid = threadIdx.x;
    const int tx = tid & 15;        // 0..15 -> N dim
    const int ty = tid >> 4;        // 0..15 -> M dim

    float acc[8][8];
#pragma unroll
    for (int i = 0; i < 8; i++)
#pragma unroll
        for (int j = 0; j < 8; j++) acc[i][j] = 0.f;

    for (int k0 = 0; k0 < K; k0 += BK) {
#pragma unroll
        for (int it = 0; it < 2; it++) {
            int v = tid + it * 256;           // 0..511
            int row = v >> 2;                 // 0..127
            int kc = (v & 3) << 2;            // 0,4,8,12
            float4 av = *(const float4*)(A + (size_t)(bm + row) * K + k0 + kc);
            As[kc + 0][row] = av.x; As[kc + 1][row] = av.y;
            As[kc + 2][row] = av.z; As[kc + 3][row] = av.w;
            float4 bv = *(const float4*)(W + (size_t)(bn + row) * K + k0 + kc);
            Bs[kc + 0][row] = bv.x; Bs[kc + 1][row] = bv.y;
            Bs[kc + 2][row] = bv.z; Bs[kc + 3][row] = bv.w;
        }
        __syncthreads();

#pragma unroll
        for (int kk = 0; kk < BK; kk++) {
            float af[8], bf[8];
#pragma unroll
            for (int i = 0; i < 8; i++) af[i] = As[kk][ty * 8 + i];
#pragma unroll
            for (int j = 0; j < 8; j++) bf[j] = Bs[kk][tx * 8 + j];
#pragma unroll
            for (int i = 0; i < 8; i++)
#pragma unroll
                for (int j = 0; j < 8; j++) acc[i][j] = fmaf(af[i], bf[j], acc[i][j]);
        }
        __syncthreads();
    }

    // epilogue
#pragma unroll
    for (int i = 0; i < 8; i++) {
        int row = bm + ty * 8 + i;
        unsigned char mrow = (EPI == E_MASK) ? mask[row] : 0;
#pragma unroll
        for (int j = 0; j < 8; j++) {
            int col = bn + tx * 8 + j;
            float c = acc[i][j] + bias[col];
            if (EPI == E_MASK && mrow) c = 0.f;
            if (EPI == E_RELU) c = fmaxf(c, 0.f);
            if (EPI == E_ADD) c += add[(size_t)row * N + col];
            C[(size_t)row * N + col] = c;
        }
    }
}

// ---------------- softmax over 16 points per (token, head) ----------------
// grid = Mrows, block = 128 (8 heads * 16 points). In-place on g_attn.
__global__ void softmax16_kernel(float* __restrict__ attn) {
    int m = blockIdx.x;
    int t = threadIdx.x;
    float v = attn[(size_t)m * 128 + t];
    float mx = v;
#pragma unroll
    for (int o = 8; o; o >>= 1) mx = fmaxf(mx, __shfl_xor_sync(0xffffffffu, mx, o, 16));
    float e = __expf(v - mx);
    float s = e;
#pragma unroll
    for (int o = 8; o; o >>= 1) s += __shfl_xor_sync(0xffffffffu, s, o, 16);
    attn[(size_t)m * 128 + t] = e / s;
}

// ---------------- msdeform bilinear sampling ----------------
// grid = Mrows, block = 256 (8 warps = heads, lane = channel within head).
__global__ void sample_kernel(const float* __restrict__ ref) {
    int m = blockIdx.x;                 // global token row
    int b = m / NTOK;
    int h = threadIdx.x >> 5;
    int d = threadIdx.x & 31;

    const float* offp  = g_off  + (size_t)m * Dd + h * (NLl * NPp * 2);
    const float* attnp = g_attn + (size_t)m * 128 + h * (NLl * NPp);
    const float* refp  = ref + (size_t)m * (NLl * 2);

    float acc = 0.f;
#pragma unroll
    for (int l = 0; l < NLl; l++) {
        int Wl = c_lvl_W[l];
        float rx = refp[l * 2 + 0];
        float ry = refp[l * 2 + 1];
        const float* vbase = g_value + ((size_t)(b * NTOK + c_lvl_start[l])) * Dd + h * DHh + d;
#pragma unroll
        for (int p = 0; p < NPp; p++) {
            float ox = offp[(l * NPp + p) * 2 + 0];
            float oy = offp[(l * NPp + p) * 2 + 1];
            float aw = attnp[l * NPp + p];
            // loc*W - 0.5 simplifies: (ref + off/W)*W - 0.5 = ref*W + off - 0.5
            float x = fmaf(rx, (float)Wl, ox) - 0.5f;
            float y = fmaf(ry, (float)Wl, oy) - 0.5f;
            float x0f = floorf(x), y0f = floorf(y);
            float fx = x - x0f, fy = y - y0f;
            int x0 = (int)x0f, y0 = (int)y0f;
            int x1 = x0 + 1, y1 = y0 + 1;
            bool vx0 = (x0 >= 0) & (x0 < Wl);
            bool vx1 = (x1 >= 0) & (x1 < Wl);
            bool vy0 = (y0 >= 0) & (y0 < Wl);
            bool vy1 = (y1 >= 0) & (y1 < Wl);
            if (vy0) {
                if (vx0) acc += aw * (1.f - fx) * (1.f - fy) * vbase[(size_t)(y0 * Wl + x0) * Dd];
                if (vx1) acc += aw * fx        * (1.f - fy) * vbase[(size_t)(y0 * Wl + x1) * Dd];
            }
            if (vy1) {
                if (vx0) acc += aw * (1.f - fx) * fy * vbase[(size_t)(y1 * Wl + x0) * Dd];
                if (vx1) acc += aw * fx        * fy * vbase[(size_t)(y1 * Wl + x1) * Dd];
            }
        }
    }
    g_a[(size_t)m * Dd + h * DHh + d] = acc;
}

// ---------------- LayerNorm over D=256 ----------------
// grid = Mrows, block = 256.
__global__ void ln_kernel(const float* __restrict__ in, const float* __restrict__ g,
                          const float* __restrict__ be, float* __restrict__ out) {
    int m = blockIdx.x;
    int t = threadIdx.x;
    float v = in[(size_t)m * Dd + t];
    float s = v, sq = v * v;
#pragma unroll
    for (int o = 16; o; o >>= 1) {
        s += __shfl_xor_sync(0xffffffffu, s, o);
        sq += __shfl_xor_sync(0xffffffffu, sq, o);
    }
    __shared__ float ss[8], ssq[8];
    __shared__ float s_mean, s_rstd;
    if ((t & 31) == 0) { ss[t >> 5] = s; ssq[t >> 5] = sq; }
    __syncthreads();
    if (t == 0) {
        float ts = 0.f, tsq = 0.f;
#pragma unroll
        for (int i = 0; i < 8; i++) { ts += ss[i]; tsq += ssq[i]; }
        float mean = ts * (1.f / Dd);
        float var = tsq * (1.f / Dd) - mean * mean;
        s_mean = mean;
        s_rstd = rsqrtf(var + 1e-5f);
    }
    __syncthreads();
    out[(size_t)m * Dd + t] = (v - s_mean) * s_rstd * g[t] + be[t];
}

// ---------------- launch ----------------
extern "C" void kernel_launch(void* const* d_in, const int* in_sizes, int n_in,
                              void* d_out, int out_size) {
    const float* src   = (const float*)d_in[0];
    const float* pos   = (const float*)d_in[1];
    const float* ref   = (const float*)d_in[2];
    const float* w_val = (const float*)d_in[3];
    const float* b_val = (const float*)d_in[4];
    const float* w_off = (const float*)d_in[5];
    const float* b_off = (const float*)d_in[6];
    const float* w_att = (const float*)d_in[7];
    const float* b_att = (const float*)d_in[8];
    const float* w_out = (const float*)d_in[9];
    const float* b_out = (const float*)d_in[10];
    const float* g1    = (const float*)d_in[11];
    const float* be1   = (const float*)d_in[12];
    const float* w1    = (const float*)d_in[13];
    const float* b1    = (const float*)d_in[14];
    const float* w2    = (const float*)d_in[15];
    const float* b2    = (const float*)d_in[16];
    const float* g2    = (const float*)d_in[17];
    const float* be2   = (const float*)d_in[18];
    const unsigned char* mask = (const unsigned char*)d_in[21];

    float *p_q, *p_value, *p_off, *p_attn, *p_a, *p_t1, *p_x, *p_h, *p_t2;
    cudaGetSymbolAddress((void**)&p_q, g_q);
    cudaGetSymbolAddress((void**)&p_value, g_value);
    cudaGetSymbolAddress((void**)&p_off, g_off);
    cudaGetSymbolAddress((void**)&p_attn, g_attn);
    cudaGetSymbolAddress((void**)&p_a, g_a);
    cudaGetSymbolAddress((void**)&p_t1, g_t1);
    cudaGetSymbolAddress((void**)&p_x, g_x);
    cudaGetSymbolAddress((void**)&p_h, g_h);
    cudaGetSymbolAddress((void**)&p_t2, g_t2);

    const int M = Mrows;

    // q = src + pos   (M*256/4 float4 elements)
    add_kernel<<<(M * Dd / 4) / 256, 256>>>(src, pos, p_q);

    // value = mask(src @ Wv^T + b)
    sgemm_kernel<E_MASK><<<dim3(Dd / BN, M / BM), 256>>>(src, w_val, b_val, p_value,
                                                         M, Dd, Dd, nullptr, mask);
    // off = q @ Woff^T + b
    sgemm_kernel<E_NONE><<<dim3(Dd / BN, M / BM), 256>>>(p_q, w_off, b_off, p_off,
                                                         M, Dd, Dd, nullptr, nullptr);
    // attn logits = q @ Wattn^T + b
    sgemm_kernel<E_NONE><<<dim3(128 / BN, M / BM), 256>>>(p_q, w_att, b_att, p_attn,
                                                          M, 128, Dd, nullptr, nullptr);
    // softmax over 16 per (token, head)
    softmax16_kernel<<<M, 128>>>(p_attn);

    // msdeform sampling -> a
    sample_kernel<<<M, 256>>>(ref);

    // t1 = src + a @ Wout^T + b
    sgemm_kernel<E_ADD><<<dim3(Dd / BN, M / BM), 256>>>(p_a, w_out, b_out, p_t1,
                                                        M, Dd, Dd, src, nullptr);
    // x = LN(t1)
    ln_kernel<<<M, 256>>>(p_t1, g1, be1, p_x);

    // h = relu(x @ W1^T + b1)
    sgemm_kernel<E_RELU><<<dim3(FFd / BN, M / BM), 256>>>(p_x, w1, b1, p_h,
                                                          M, FFd, Dd, nullptr, nullptr);
    // t2 = x + h @ W2^T + b2
    sgemm_kernel<E_ADD><<<dim3(Dd / BN, M / BM), 256>>>(p_h, w2, b2, p_t2,
                                                        M, Dd, FFd, p_x, nullptr);
    // out = LN(t2)
    ln_kernel<<<M, 256>>>(p_t2, g2, be2, (float*)d_out);
}

// round 3
// speedup vs baseline: 1.8388x; 1.8388x over previous
#include <cuda_runtime.h>
#include <cuda_bf16.h>
#include <math.h>
#include <stdint.h>

typedef __nv_bfloat16 bf16;

// ---------------- problem constants ----------------
#define Bb 4
#define NTOK 5440
#define Mrows (Bb * NTOK)   // 21760
#define Dd 256
#define FFd 1024
#define NHh 8
#define NLl 4
#define NPp 4
#define DHh 32

__device__ __constant__ int c_lvl_W[4]     = {64, 32, 16, 8};
__device__ __constant__ int c_lvl_start[4] = {0, 4096, 5120, 5376};

// ---------------- scratch (device globals) ----------------
__device__ bf16  g_srch[Mrows * Dd], g_srcl[Mrows * Dd];
__device__ bf16  g_qh  [Mrows * Dd], g_ql  [Mrows * Dd];
__device__ bf16  g_ah  [Mrows * Dd], g_al  [Mrows * Dd];
__device__ bf16  g_xh  [Mrows * Dd], g_xl  [Mrows * Dd];
__device__ bf16  g_hh  [Mrows * FFd], g_hl [Mrows * FFd];
__device__ float g_value[Mrows * Dd];
__device__ float g_off  [Mrows * Dd];
__device__ float g_attn [Mrows * 128];
__device__ float g_t1   [Mrows * Dd];
__device__ float g_x    [Mrows * Dd];
__device__ float g_t2   [Mrows * Dd];
// split weights
__device__ bf16 g_wvh[Dd*Dd],  g_wvl[Dd*Dd];
__device__ bf16 g_wofh[Dd*Dd], g_wofl[Dd*Dd];
__device__ bf16 g_wath[128*Dd],g_watl[128*Dd];
__device__ bf16 g_woh[Dd*Dd],  g_wol[Dd*Dd];
__device__ bf16 g_w1h[FFd*Dd], g_w1l[FFd*Dd];
__device__ bf16 g_w2h[Dd*FFd], g_w2l[Dd*FFd];

// ---------------- helpers ----------------
__device__ __forceinline__ uint32_t smem_u32(const void* p) {
    uint32_t a;
    asm("{ .reg .u64 t; cvta.to.shared.u64 t, %1; cvt.u32.u64 %0, t; }" : "=r"(a) : "l"(p));
    return a;
}

#define CP_ASYNC16(saddr, gptr) \
    asm volatile("cp.async.cg.shared.global [%0], [%1], 16;" :: "r"(saddr), "l"(gptr))
#define CP_COMMIT() asm volatile("cp.async.commit_group;" ::: "memory")

__device__ __forceinline__ void mma16816(float* d, const uint32_t* a, const uint32_t* b) {
    asm volatile("mma.sync.aligned.m16n8k16.row.col.f32.bf16.bf16.f32 "
        "{%0,%1,%2,%3}, {%4,%5,%6,%7}, {%8,%9}, {%0,%1,%2,%3};"
        : "+f"(d[0]), "+f"(d[1]), "+f"(d[2]), "+f"(d[3])
        : "r"(a[0]), "r"(a[1]), "r"(a[2]), "r"(a[3]), "r"(b[0]), "r"(b[1]));
}

// split a float into hi/lo bf16
__device__ __forceinline__ void splitf(float v, bf16& h, bf16& l) {
    h = __float2bfloat16(v);
    l = __float2bfloat16(v - __bfloat162float(h));
}
__device__ __forceinline__ void split4(float4 v, uint2& hi, uint2& lo) {
    bf16 h0, l0, h1, l1, h2, l2, h3, l3;
    splitf(v.x, h0, l0); splitf(v.y, h1, l1);
    splitf(v.z, h2, l2); splitf(v.w, h3, l3);
    __nv_bfloat162 a, b;
    a.x = h0; a.y = h1; b.x = h2; b.y = h3;
    hi.x = *(uint32_t*)&a; hi.y = *(uint32_t*)&b;
    a.x = l0; a.y = l1; b.x = l2; b.y = l3;
    lo.x = *(uint32_t*)&a; lo.y = *(uint32_t*)&b;
}
__device__ __forceinline__ void split2(float x, float y, uint32_t& hi, uint32_t& lo) {
    bf16 hx, lx, hy, ly;
    splitf(x, hx, lx); splitf(y, hy, ly);
    __nv_bfloat162 a;
    a.x = hx; a.y = hy; hi = *(uint32_t*)&a;
    a.x = lx; a.y = ly; lo = *(uint32_t*)&a;
}

__global__ void split_kernel(const float* __restrict__ x, bf16* __restrict__ h,
                             bf16* __restrict__ l, int n4) {
    int i = blockIdx.x * blockDim.x + threadIdx.x;
    if (i >= n4) return;
    uint2 hi, lo;
    split4(((const float4*)x)[i], hi, lo);
    ((uint2*)h)[i] = hi;
    ((uint2*)l)[i] = lo;
}

__global__ void add_split_kernel(const float* __restrict__ a, const float* __restrict__ b,
                                 bf16* __restrict__ h, bf16* __restrict__ l) {
    int i = blockIdx.x * blockDim.x + threadIdx.x;
    float4 va = ((const float4*)a)[i];
    float4 vb = ((const float4*)b)[i];
    float4 v = make_float4(va.x + vb.x, va.y + vb.y, va.z + vb.z, va.w + vb.w);
    uint2 hi, lo;
    split4(v, hi, lo);
    ((uint2*)h)[i] = hi;
    ((uint2*)l)[i] = lo;
}

// ---------------- HMMA GEMM ----------------
// C[M,N] = (Ah+Al)[M,K] @ (Bh+Bl)[N,K]^T  (3-term split), fused epilogue.
// CTA 128x128, K-chunk 32, 256 threads (8 warps 2x4), warp tile 64x32.
// SMEM rows: 32 bf16 = 64B data + 16B pad = 80B stride (conflict-free).
#define ARRB   (128 * 80)     // one operand tile per stage
#define STAGEB (4 * ARRB)     // Ah, Al, Bh, Bl

enum { E_NONE = 0, E_MASK = 1, E_ADD = 2, E_RELU_SPLIT = 3 };

template <int EPI>
__global__ __launch_bounds__(256, 1)
void tc_gemm(const bf16* __restrict__ Ah, const bf16* __restrict__ Al,
             const bf16* __restrict__ Bh, const bf16* __restrict__ Bl,
             const float* __restrict__ bias, float* __restrict__ C,
             bf16* __restrict__ Ch, bf16* __restrict__ Cl,
             int M, int N, int K,
             const float* __restrict__ add, const unsigned char* __restrict__ mask) {
    extern __shared__ char sm[];
    const uint32_t smb = smem_u32(sm);

    const int tid = threadIdx.x;
    const int wid = tid >> 5, lane = tid & 31;
    const int wm = wid & 1, wn = wid >> 1;          // warp 64x32 tile
    const int g = lane >> 2, t = lane & 3;
    const int bm = blockIdx.y * 128;
    const int bn = blockIdx.x * 128;

    const int nchunks = K >> 5;

    // async loader for one chunk into a stage
    auto load_chunk = [&](int stage, int c) {
        const uint32_t sb = smb + stage * STAGEB;
        const size_t kb = (size_t)c * 32;
#pragma unroll
        for (int it = 0; it < 8; it++) {
            int i = tid + it * 256;
            int arr = i >> 9;
            int j = i & 511;
            int row = j >> 2, q = j & 3;
            uint32_t soff = (uint32_t)arr * ARRB + row * 80 + q * 16;
            const bf16* gp = (arr == 0) ? Ah : (arr == 1) ? Al : (arr == 2) ? Bh : Bl;
            int grow = (arr < 2) ? (bm + row) : (bn + row);
            const char* gaddr = (const char*)(gp + (size_t)grow * K + kb) + q * 16;
            CP_ASYNC16(sb + soff, gaddr);
        }
        CP_COMMIT();
    };

    float acc[4][4][4];
#pragma unroll
    for (int i = 0; i < 4; i++)
#pragma unroll
        for (int j = 0; j < 4; j++)
#pragma unroll
            for (int r = 0; r < 4; r++) acc[i][j][r] = 0.f;

    load_chunk(0, 0);
    if (nchunks > 1) load_chunk(1, 1);

    for (int c = 0; c < nchunks; c++) {
        if (c < nchunks - 1) asm volatile("cp.async.wait_group 1;" ::: "memory");
        else                 asm volatile("cp.async.wait_group 0;" ::: "memory");
        __syncthreads();

        const char* st = sm + (c & 1) * STAGEB;
#pragma unroll
        for (int ks = 0; ks < 2; ks++) {
            const int kb2 = ks * 32;     // byte offset of k-step within 64B row
            uint32_t Af[4][4], Alf[4][4], Bf[4][2], Blf[4][2];
#pragma unroll
            for (int i = 0; i < 4; i++) {
                int off = (wm * 64 + i * 16 + g) * 80 + kb2 + 4 * t;
                Af[i][0]  = *(const uint32_t*)(st + off);
                Af[i][1]  = *(const uint32_t*)(st + off + 640);
                Af[i][2]  = *(const uint32_t*)(st + off + 16);
                Af[i][3]  = *(const uint32_t*)(st + off + 656);
                Alf[i][0] = *(const uint32_t*)(st + ARRB + off);
                Alf[i][1] = *(const uint32_t*)(st + ARRB + off + 640);
                Alf[i][2] = *(const uint32_t*)(st + ARRB + off + 16);
                Alf[i][3] = *(const uint32_t*)(st + ARRB + off + 656);
            }
#pragma unroll
            for (int j = 0; j < 4; j++) {
                int off = (wn * 32 + j * 8 + g) * 80 + kb2 + 4 * t;
                Bf[j][0]  = *(const uint32_t*)(st + 2 * ARRB + off);
                Bf[j][1]  = *(const uint32_t*)(st + 2 * ARRB + off + 16);
                Blf[j][0] = *(const uint32_t*)(st + 3 * ARRB + off);
                Blf[j][1] = *(const uint32_t*)(st + 3 * ARRB + off + 16);
            }
#pragma unroll
            for (int i = 0; i < 4; i++)
#pragma unroll
                for (int j = 0; j < 4; j++) {
                    mma16816(acc[i][j], Af[i],  Bf[j]);
                    mma16816(acc[i][j], Alf[i], Bf[j]);
                    mma16816(acc[i][j], Af[i],  Blf[j]);
                }
        }
        __syncthreads();
        if (c + 2 < nchunks) load_chunk(c & 1, c + 2);
    }

    // ---------------- epilogue ----------------
#pragma unroll
    for (int i = 0; i < 4; i++) {
        int row0 = bm + wm * 64 + i * 16 + g;
#pragma unroll
        for (int j = 0; j < 4; j++) {
            int col = bn + wn * 32 + j * 8 + 2 * t;
            float b0 = bias[col], b1 = bias[col + 1];
#pragma unroll
            for (int half = 0; half < 2; half++) {
                int row = row0 + half * 8;
                float v0 = acc[i][j][half * 2 + 0] + b0;
                float v1 = acc[i][j][half * 2 + 1] + b1;
                if (EPI == E_MASK) {
                    if (mask[row]) { v0 = 0.f; v1 = 0.f; }
                    *(float2*)(C + (size_t)row * N + col) = make_float2(v0, v1);
                } else if (EPI == E_ADD) {
                    float2 r2 = *(const float2*)(add + (size_t)row * N + col);
                    *(float2*)(C + (size_t)row * N + col) = make_float2(v0 + r2.x, v1 + r2.y);
                } else if (EPI == E_RELU_SPLIT) {
                    v0 = fmaxf(v0, 0.f); v1 = fmaxf(v1, 0.f);
                    uint32_t hi, lo;
                    split2(v0, v1, hi, lo);
                    *(uint32_t*)(Ch + (size_t)row * N + col) = hi;
                    *(uint32_t*)(Cl + (size_t)row * N + col) = lo;
                } else {
                    *(float2*)(C + (size_t)row * N + col) = make_float2(v0, v1);
                }
            }
        }
    }
}

// ---------------- softmax over 16 points per (token, head) ----------------
__global__ void softmax16_kernel(float* __restrict__ attn) {
    int m = blockIdx.x;
    int t = threadIdx.x;
    float v = attn[(size_t)m * 128 + t];
    float mx = v;
#pragma unroll
    for (int o = 8; o; o >>= 1) mx = fmaxf(mx, __shfl_xor_sync(0xffffffffu, mx, o, 16));
    float e = __expf(v - mx);
    float s = e;
#pragma unroll
    for (int o = 8; o; o >>= 1) s += __shfl_xor_sync(0xffffffffu, s, o, 16);
    attn[(size_t)m * 128 + t] = e / s;
}

// ---------------- msdeform bilinear sampling (writes split bf16 directly) ----------------
__global__ void sample_kernel(const float* __restrict__ ref,
                              bf16* __restrict__ ah, bf16* __restrict__ al) {
    int m = blockIdx.x;
    int b = m / NTOK;
    int h = threadIdx.x >> 5;
    int d = threadIdx.x & 31;

    const float* offp  = g_off  + (size_t)m * Dd + h * (NLl * NPp * 2);
    const float* attnp = g_attn + (size_t)m * 128 + h * (NLl * NPp);
    const float* refp  = ref + (size_t)m * (NLl * 2);

    float acc = 0.f;
#pragma unroll
    for (int l = 0; l < NLl; l++) {
        int Wl = c_lvl_W[l];
        float rx = refp[l * 2 + 0];
        float ry = refp[l * 2 + 1];
        const float* vbase = g_value + ((size_t)(b * NTOK + c_lvl_start[l])) * Dd + h * DHh + d;
#pragma unroll
        for (int p = 0; p < NPp; p++) {
            float ox = offp[(l * NPp + p) * 2 + 0];
            float oy = offp[(l * NPp + p) * 2 + 1];
            float aw = attnp[l * NPp + p];
            float x = fmaf(rx, (float)Wl, ox) - 0.5f;
            float y = fmaf(ry, (float)Wl, oy) - 0.5f;
            float x0f = floorf(x), y0f = floorf(y);
            float fx = x - x0f, fy = y - y0f;
            int x0 = (int)x0f, y0 = (int)y0f;
            int x1 = x0 + 1, y1 = y0 + 1;
            bool vx0 = (x0 >= 0) & (x0 < Wl);
            bool vx1 = (x1 >= 0) & (x1 < Wl);
            bool vy0 = (y0 >= 0) & (y0 < Wl);
            bool vy1 = (y1 >= 0) & (y1 < Wl);
            if (vy0) {
                if (vx0) acc += aw * (1.f - fx) * (1.f - fy) * vbase[(size_t)(y0 * Wl + x0) * Dd];
                if (vx1) acc += aw * fx        * (1.f - fy) * vbase[(size_t)(y0 * Wl + x1) * Dd];
            }
            if (vy1) {
                if (vx0) acc += aw * (1.f - fx) * fy * vbase[(size_t)(y1 * Wl + x0) * Dd];
                if (vx1) acc += aw * fx        * fy * vbase[(size_t)(y1 * Wl + x1) * Dd];
            }
        }
    }
    bf16 hb, lb;
    splitf(acc, hb, lb);
    ah[(size_t)m * Dd + h * DHh + d] = hb;
    al[(size_t)m * Dd + h * DHh + d] = lb;
}

// ---------------- LayerNorm over D=256 (optionally emit split bf16) ----------------
template <bool SP>
__global__ void ln_kernel(const float* __restrict__ in, const float* __restrict__ g,
                          const float* __restrict__ be, float* __restrict__ out,
                          bf16* __restrict__ oh, bf16* __restrict__ ol) {
    int m = blockIdx.x;
    int t = threadIdx.x;
    float v = in[(size_t)m * Dd + t];
    float s = v, sq = v * v;
#pragma unroll
    for (int o = 16; o; o >>= 1) {
        s += __shfl_xor_sync(0xffffffffu, s, o);
        sq += __shfl_xor_sync(0xffffffffu, sq, o);
    }
    __shared__ float ss[8], ssq[8];
    __shared__ float s_mean, s_rstd;
    if ((t & 31) == 0) { ss[t >> 5] = s; ssq[t >> 5] = sq; }
    __syncthreads();
    if (t == 0) {
        float ts = 0.f, tsq = 0.f;
#pragma unroll
        for (int i = 0; i < 8; i++) { ts += ss[i]; tsq += ssq[i]; }
        float mean = ts * (1.f / Dd);
        float var = tsq * (1.f / Dd) - mean * mean;
        s_mean = mean;
        s_rstd = rsqrtf(var + 1e-5f);
    }
    __syncthreads();
    float o = (v - s_mean) * s_rstd * g[t] + be[t];
    out[(size_t)m * Dd + t] = o;
    if (SP) {
        bf16 hb, lb;
        splitf(o, hb, lb);
        oh[(size_t)m * Dd + t] = hb;
        ol[(size_t)m * Dd + t] = lb;
    }
}

// ---------------- launch ----------------
extern "C" void kernel_launch(void* const* d_in, const int* in_sizes, int n_in,
                              void* d_out, int out_size) {
    const float* src   = (const float*)d_in[0];
    const float* pos   = (const float*)d_in[1];
    const float* ref   = (const float*)d_in[2];
    const float* w_val = (const float*)d_in[3];
    const float* b_val = (const float*)d_in[4];
    const float* w_off = (const float*)d_in[5];
    const float* b_off = (const float*)d_in[6];
    const float* w_att = (const float*)d_in[7];
    const float* b_att = (const float*)d_in[8];
    const float* w_out = (const float*)d_in[9];
    const float* b_out = (const float*)d_in[10];
    const float* g1    = (const float*)d_in[11];
    const float* be1   = (const float*)d_in[12];
    const float* w1    = (const float*)d_in[13];
    const float* b1    = (const float*)d_in[14];
    const float* w2    = (const float*)d_in[15];
    const float* b2    = (const float*)d_in[16];
    const float* g2    = (const float*)d_in[17];
    const float* be2   = (const float*)d_in[18];
    const unsigned char* mask = (const unsigned char*)d_in[21];

    bf16 *srch, *srcl, *qh, *ql, *ah, *al, *xh, *xl, *hh, *hl;
    bf16 *wvh, *wvl, *wofh, *wofl, *wath, *watl, *woh, *wol, *w1h, *w1l, *w2h, *w2l;
    float *p_value, *p_off, *p_attn, *p_t1, *p_x, *p_t2;
    cudaGetSymbolAddress((void**)&srch, g_srch);  cudaGetSymbolAddress((void**)&srcl, g_srcl);
    cudaGetSymbolAddress((void**)&qh, g_qh);      cudaGetSymbolAddress((void**)&ql, g_ql);
    cudaGetSymbolAddress((void**)&ah, g_ah);      cudaGetSymbolAddress((void**)&al, g_al);
    cudaGetSymbolAddress((void**)&xh, g_xh);      cudaGetSymbolAddress((void**)&xl, g_xl);
    cudaGetSymbolAddress((void**)&hh, g_hh);      cudaGetSymbolAddress((void**)&hl, g_hl);
    cudaGetSymbolAddress((void**)&wvh, g_wvh);    cudaGetSymbolAddress((void**)&wvl, g_wvl);
    cudaGetSymbolAddress((void**)&wofh, g_wofh);  cudaGetSymbolAddress((void**)&wofl, g_wofl);
    cudaGetSymbolAddress((void**)&wath, g_wath);  cudaGetSymbolAddress((void**)&watl, g_watl);
    cudaGetSymbolAddress((void**)&woh, g_woh);    cudaGetSymbolAddress((void**)&wol, g_wol);
    cudaGetSymbolAddress((void**)&w1h, g_w1h);    cudaGetSymbolAddress((void**)&w1l, g_w1l);
    cudaGetSymbolAddress((void**)&w2h, g_w2h);    cudaGetSymbolAddress((void**)&w2l, g_w2l);
    cudaGetSymbolAddress((void**)&p_value, g_value);
    cudaGetSymbolAddress((void**)&p_off, g_off);
    cudaGetSymbolAddress((void**)&p_attn, g_attn);
    cudaGetSymbolAddress((void**)&p_t1, g_t1);
    cudaGetSymbolAddress((void**)&p_x, g_x);
    cudaGetSymbolAddress((void**)&p_t2, g_t2);

    const int M = Mrows;
    const int SMEM = 2 * STAGEB;   // 81920
    cudaFuncSetAttribute(tc_gemm<E_MASK>,       cudaFuncAttributeMaxDynamicSharedMemorySize, SMEM);
    cudaFuncSetAttribute(tc_gemm<E_NONE>,       cudaFuncAttributeMaxDynamicSharedMemorySize, SMEM);
    cudaFuncSetAttribute(tc_gemm<E_ADD>,        cudaFuncAttributeMaxDynamicSharedMemorySize, SMEM);
    cudaFuncSetAttribute(tc_gemm<E_RELU_SPLIT>, cudaFuncAttributeMaxDynamicSharedMemorySize, SMEM);

    // splits
    split_kernel<<<(M * Dd / 4 + 255) / 256, 256>>>(src, srch, srcl, M * Dd / 4);
    add_split_kernel<<<(M * Dd / 4) / 256, 256>>>(src, pos, qh, ql);
    split_kernel<<<(Dd * Dd / 4 + 255) / 256, 256>>>(w_val, wvh, wvl, Dd * Dd / 4);
    split_kernel<<<(Dd * Dd / 4 + 255) / 256, 256>>>(w_off, wofh, wofl, Dd * Dd / 4);
    split_kernel<<<(128 * Dd / 4 + 255) / 256, 256>>>(w_att, wath, watl, 128 * Dd / 4);
    split_kernel<<<(Dd * Dd / 4 + 255) / 256, 256>>>(w_out, woh, wol, Dd * Dd / 4);
    split_kernel<<<(FFd * Dd / 4 + 255) / 256, 256>>>(w1, w1h, w1l, FFd * Dd / 4);
    split_kernel<<<(Dd * FFd / 4 + 255) / 256, 256>>>(w2, w2h, w2l, Dd * FFd / 4);

    // value = mask(src @ Wv^T + b)
    tc_gemm<E_MASK><<<dim3(Dd / 128, M / 128), 256, SMEM>>>(
        srch, srcl, wvh, wvl, b_val, p_value, nullptr, nullptr, M, Dd, Dd, nullptr, mask);
    // off = q @ Woff^T + b
    tc_gemm<E_NONE><<<dim3(Dd / 128, M / 128), 256, SMEM>>>(
        qh, ql, wofh, wofl, b_off, p_off, nullptr, nullptr, M, Dd, Dd, nullptr, nullptr);
    // attn logits = q @ Wattn^T + b
    tc_gemm<E_NONE><<<dim3(1, M / 128), 256, SMEM>>>(
        qh, ql, wath, watl, b_att, p_attn, nullptr, nullptr, M, 128, Dd, nullptr, nullptr);
    softmax16_kernel<<<M, 128>>>(p_attn);
    sample_kernel<<<M, 256>>>(ref, ah, al);
    // t1 = src + a @ Wout^T + b
    tc_gemm<E_ADD><<<dim3(Dd / 128, M / 128), 256, SMEM>>>(
        ah, al, woh, wol, b_out, p_t1, nullptr, nullptr, M, Dd, Dd, src, nullptr);
    // x = LN(t1) (+ split)
    ln_kernel<true><<<M, 256>>>(p_t1, g1, be1, p_x, xh, xl);
    // h = relu(x @ W1^T + b1) -> split bf16 directly
    tc_gemm<E_RELU_SPLIT><<<dim3(FFd / 128, M / 128), 256, SMEM>>>(
        xh, xl, w1h, w1l, b1, nullptr, hh, hl, M, FFd, Dd, nullptr, nullptr);
    // t2 = x + h @ W2^T + b2
    tc_gemm<E_ADD><<<dim3(Dd / 128, M / 128), 256, SMEM>>>(
        hh, hl, w2h, w2l, b2, p_t2, nullptr, nullptr, M, Dd, FFd, p_x, nullptr);
    // out = LN(t2)
    ln_kernel<false><<<M, 256>>>(p_t2, g2, be2, (float*)d_out, nullptr, nullptr);
}

// round 4
// speedup vs baseline: 1.8958x; 1.0310x over previous
#include <cuda_runtime.h>
#include <cuda_bf16.h>
#include <math.h>
#include <stdint.h>

typedef __nv_bfloat16 bf16;

// ---------------- problem constants ----------------
#define Bb 4
#define NTOK 5440
#define Mrows (Bb * NTOK)   // 21760
#define Dd 256
#define FFd 1024
#define NHh 8
#define NLl 4
#define NPp 4
#define DHh 32

__device__ __constant__ int c_lvl_W[4]     = {64, 32, 16, 8};
__device__ __constant__ int c_lvl_start[4] = {0, 4096, 5120, 5376};

// ---------------- scratch (device globals) ----------------
__device__ bf16  g_srch[Mrows * Dd], g_srcl[Mrows * Dd];
__device__ bf16  g_qh  [Mrows * Dd], g_ql  [Mrows * Dd];
__device__ bf16  g_ah  [Mrows * Dd], g_al  [Mrows * Dd];
__device__ bf16  g_xh  [Mrows * Dd], g_xl  [Mrows * Dd];
__device__ bf16  g_hh  [Mrows * FFd], g_hl [Mrows * FFd];
__device__ bf16  g_valbf[Mrows * Dd];          // value in bf16 (sampler-facing)
__device__ float g_off  [Mrows * Dd];
__device__ float g_attn [Mrows * 128];          // logits (softmax fused into sampler)
__device__ float g_t1   [Mrows * Dd];
__device__ float g_x    [Mrows * Dd];
__device__ float g_t2   [Mrows * Dd];
// split weights
__device__ bf16 g_wvh[Dd*Dd],    g_wvl[Dd*Dd];
__device__ bf16 g_wch[384*Dd],   g_wcl[384*Dd];   // [w_off ; w_attn] packed, 384 rows
__device__ bf16 g_woh[Dd*Dd],    g_wol[Dd*Dd];
__device__ bf16 g_w1h[FFd*Dd],   g_w1l[FFd*Dd];
__device__ bf16 g_w2h[Dd*FFd],   g_w2l[Dd*FFd];
__device__ float g_bcomb[384];                    // [b_off ; b_attn]

// ---------------- helpers ----------------
__device__ __forceinline__ uint32_t smem_u32(const void* p) {
    uint32_t a;
    asm("{ .reg .u64 t; cvta.to.shared.u64 t, %1; cvt.u32.u64 %0, t; }" : "=r"(a) : "l"(p));
    return a;
}

#define CP_ASYNC16(saddr, gptr) \
    asm volatile("cp.async.cg.shared.global [%0], [%1], 16;" :: "r"(saddr), "l"(gptr))
#define CP_COMMIT() asm volatile("cp.async.commit_group;" ::: "memory")

__device__ __forceinline__ void ldsm4(uint32_t* r, uint32_t a) {
    asm volatile("ldmatrix.sync.aligned.m8n8.x4.shared.b16 {%0,%1,%2,%3}, [%4];"
        : "=r"(r[0]), "=r"(r[1]), "=r"(r[2]), "=r"(r[3]) : "r"(a));
}

__device__ __forceinline__ void mma16816(float* d, const uint32_t* a, const uint32_t* b) {
    asm volatile("mma.sync.aligned.m16n8k16.row.col.f32.bf16.bf16.f32 "
        "{%0,%1,%2,%3}, {%4,%5,%6,%7}, {%8,%9}, {%0,%1,%2,%3};"
        : "+f"(d[0]), "+f"(d[1]), "+f"(d[2]), "+f"(d[3])
        : "r"(a[0]), "r"(a[1]), "r"(a[2]), "r"(a[3]), "r"(b[0]), "r"(b[1]));
}

__device__ __forceinline__ void splitf(float v, bf16& h, bf16& l) {
    h = __float2bfloat16(v);
    l = __float2bfloat16(v - __bfloat162float(h));
}
__device__ __forceinline__ void split4(float4 v, uint2& hi, uint2& lo) {
    bf16 h0, l0, h1, l1, h2, l2, h3, l3;
    splitf(v.x, h0, l0); splitf(v.y, h1, l1);
    splitf(v.z, h2, l2); splitf(v.w, h3, l3);
    __nv_bfloat162 a, b;
    a.x = h0; a.y = h1; b.x = h2; b.y = h3;
    hi.x = *(uint32_t*)&a; hi.y = *(uint32_t*)&b;
    a.x = l0; a.y = l1; b.x = l2; b.y = l3;
    lo.x = *(uint32_t*)&a; lo.y = *(uint32_t*)&b;
}
__device__ __forceinline__ void split2(float x, float y, uint32_t& hi, uint32_t& lo) {
    bf16 hx, lx, hy, ly;
    splitf(x, hx, lx); splitf(y, hy, ly);
    __nv_bfloat162 a;
    a.x = hx; a.y = hy; hi = *(uint32_t*)&a;
    a.x = lx; a.y = ly; lo = *(uint32_t*)&a;
}

// ---------------- prep kernels ----------------
// src + pos fused split: one pass, 4 outputs
__global__ void src_q_split(const float* __restrict__ src, const float* __restrict__ pos,
                            bf16* __restrict__ sh, bf16* __restrict__ sl,
                            bf16* __restrict__ qh, bf16* __restrict__ ql) {
    int i = blockIdx.x * blockDim.x + threadIdx.x;
    float4 s = ((const float4*)src)[i];
    float4 p = ((const float4*)pos)[i];
    uint2 hi, lo;
    split4(s, hi, lo);
    ((uint2*)sh)[i] = hi; ((uint2*)sl)[i] = lo;
    float4 q = make_float4(s.x + p.x, s.y + p.y, s.z + p.z, s.w + p.w);
    split4(q, hi, lo);
    ((uint2*)qh)[i] = hi; ((uint2*)ql)[i] = lo;
}

struct WSplitArgs {
    const float* s[6];
    bf16* h[6];
    bf16* l[6];
    int n4[6];
};
__global__ void wsplit_all(WSplitArgs a) {
    int seg = blockIdx.y;
    int i = blockIdx.x * blockDim.x + threadIdx.x;
    if (i >= a.n4[seg]) return;
    uint2 hi, lo;
    split4(((const float4*)a.s[seg])[i], hi, lo);
    ((uint2*)a.h[seg])[i] = hi;
    ((uint2*)a.l[seg])[i] = lo;
}

__global__ void pack_bias(const float* __restrict__ bo, const float* __restrict__ ba,
                          float* __restrict__ dst) {
    int i = threadIdx.x;
    dst[i] = (i < 256) ? bo[i] : ba[i - 256];
}

// ---------------- HMMA GEMM ----------------
// C[M,N] = (Ah+Al)[M,K] @ (Bh+Bl)[N,K]^T  (3-term split), fused epilogue.
// CTA 128x128, K-chunk 32, 256 threads (8 warps 2x4), warp tile 64x32.
// SMEM rows: 32 bf16 = 64B + 16B pad = 80B stride. 3-stage cp.async pipeline.
#define ARRB   (128 * 80)
#define STAGEB (4 * ARRB)
#define NSTAGE 3

enum { E_MASK_BF16 = 0, E_OFFATTN = 1, E_ADD = 2, E_RELU_SPLIT = 3 };

template <int EPI>
__global__ __launch_bounds__(256, 1)
void tc_gemm(const bf16* __restrict__ Ah, const bf16* __restrict__ Al,
             const bf16* __restrict__ Bh, const bf16* __restrict__ Bl,
             const float* __restrict__ bias,
             float* __restrict__ outF, float* __restrict__ outF2,
             bf16* __restrict__ outBFh, bf16* __restrict__ outBFl,
             int M, int N, int K,
             const float* __restrict__ add, const unsigned char* __restrict__ mask) {
    extern __shared__ char sm[];
    const uint32_t smb = smem_u32(sm);

    const int tid = threadIdx.x;
    const int wid = tid >> 5, lane = tid & 31;
    const int wm = wid & 1, wn = wid >> 1;      // warp 64x32 tile
    const int g = lane >> 2, t = lane & 3;
    const int bm = blockIdx.y * 128;
    const int bn = blockIdx.x * 128;

    const int nchunks = K >> 5;

    auto load_chunk = [&](int stage, int c) {
        const uint32_t sb = smb + stage * STAGEB;
        const size_t kb = (size_t)c * 32;
#pragma unroll
        for (int it = 0; it < 8; it++) {
            int i = tid + it * 256;
            int arr = i >> 9;
            int j = i & 511;
            int row = j >> 2, q = j & 3;
            uint32_t soff = (uint32_t)arr * ARRB + row * 80 + q * 16;
            const bf16* gp = (arr == 0) ? Ah : (arr == 1) ? Al : (arr == 2) ? Bh : Bl;
            int grow = (arr < 2) ? (bm + row) : (bn + row);
            const char* gaddr = (const char*)(gp + (size_t)grow * K + kb) + q * 16;
            CP_ASYNC16(sb + soff, gaddr);
        }
        CP_COMMIT();
    };

    float acc[4][4][4];
#pragma unroll
    for (int i = 0; i < 4; i++)
#pragma unroll
        for (int j = 0; j < 4; j++)
#pragma unroll
            for (int r = 0; r < 4; r++) acc[i][j][r] = 0.f;

    load_chunk(0, 0);
    load_chunk(1, 1);

    // ldmatrix lane offsets (byte)
    const uint32_t a_lane = (uint32_t)(lane & 15) * 80 + (uint32_t)(lane >> 4) * 16;
    const uint32_t b_lane = (uint32_t)(((lane >> 4) & 1) * 8 + (lane & 7)) * 80
                          + (uint32_t)((lane >> 3) & 1) * 16;

    for (int c = 0; c < nchunks; c++) {
        if (c == nchunks - 1) asm volatile("cp.async.wait_group 0;" ::: "memory");
        else                  asm volatile("cp.async.wait_group 1;" ::: "memory");
        __syncthreads();
        if (c + 2 < nchunks) load_chunk((c + 2) % NSTAGE, c + 2);

        const uint32_t stg = smb + (c % NSTAGE) * STAGEB;
        const uint32_t aA = stg + (uint32_t)(wm * 64) * 80 + a_lane;
        const uint32_t aB = stg + 2 * ARRB + (uint32_t)(wn * 32) * 80 + b_lane;
#pragma unroll
        for (int ks = 0; ks < 2; ks++) {
            const uint32_t kb = ks * 32;
            uint32_t Ahf[4][4], Alf[4][4], Bhf[2][4], Blf[2][4];
#pragma unroll
            for (int i = 0; i < 4; i++) {
                ldsm4(Ahf[i], aA + i * (16 * 80) + kb);
                ldsm4(Alf[i], aA + ARRB + i * (16 * 80) + kb);
            }
#pragma unroll
            for (int p = 0; p < 2; p++) {
                ldsm4(Bhf[p], aB + p * (16 * 80) + kb);
                ldsm4(Blf[p], aB + ARRB + p * (16 * 80) + kb);
            }
#pragma unroll
            for (int i = 0; i < 4; i++)
#pragma unroll
                for (int j = 0; j < 4; j++) {
                    const uint32_t* bh = &Bhf[j >> 1][(j & 1) * 2];
                    const uint32_t* bl = &Blf[j >> 1][(j & 1) * 2];
                    mma16816(acc[i][j], Ahf[i], bh);
                    mma16816(acc[i][j], Alf[i], bh);
                    mma16816(acc[i][j], Ahf[i], bl);
                }
        }
        __syncthreads();
    }

    // ---------------- epilogue ----------------
#pragma unroll
    for (int i = 0; i < 4; i++) {
        int row0 = bm + wm * 64 + i * 16 + g;
#pragma unroll
        for (int j = 0; j < 4; j++) {
            int col = bn + wn * 32 + j * 8 + 2 * t;
            float b0 = bias[col], b1 = bias[col + 1];
#pragma unroll
            for (int half = 0; half < 2; half++) {
                int row = row0 + half * 8;
                float v0 = acc[i][j][half * 2 + 0] + b0;
                float v1 = acc[i][j][half * 2 + 1] + b1;
                if (EPI == E_MASK_BF16) {
                    if (mask[row]) { v0 = 0.f; v1 = 0.f; }
                    __nv_bfloat162 pk;
                    pk.x = __float2bfloat16(v0); pk.y = __float2bfloat16(v1);
                    *(uint32_t*)(outBFh + (size_t)row * N + col) = *(uint32_t*)&pk;
                } else if (EPI == E_OFFATTN) {
                    if (bn == 256)
                        *(float2*)(outF2 + (size_t)row * 128 + (col - 256)) = make_float2(v0, v1);
                    else
                        *(float2*)(outF + (size_t)row * 256 + col) = make_float2(v0, v1);
                } else if (EPI == E_ADD) {
                    float2 r2 = *(const float2*)(add + (size_t)row * N + col);
                    *(float2*)(outF + (size_t)row * N + col) = make_float2(v0 + r2.x, v1 + r2.y);
                } else if (EPI == E_RELU_SPLIT) {
                    v0 = fmaxf(v0, 0.f); v1 = fmaxf(v1, 0.f);
                    uint32_t hi, lo;
                    split2(v0, v1, hi, lo);
                    *(uint32_t*)(outBFh + (size_t)row * N + col) = hi;
                    *(uint32_t*)(outBFl + (size_t)row * N + col) = lo;
                }
            }
        }
    }
}

// ---------------- msdeform sampling (softmax fused, bf16 value, split out) ----------------
__global__ void sample_kernel(const float* __restrict__ ref,
                              bf16* __restrict__ ah, bf16* __restrict__ al) {
    int m = blockIdx.x;
    int b = m / NTOK;
    int h = threadIdx.x >> 5;
    int lane = threadIdx.x & 31;

    // fused softmax over this head's 16 logits
    const float* logp = g_attn + (size_t)m * 128 + h * 16;
    float logit = (lane < 16) ? logp[lane] : -1e30f;
    float mx = logit;
#pragma unroll
    for (int o = 8; o; o >>= 1) mx = fmaxf(mx, __shfl_xor_sync(0xffffffffu, mx, o, 16));
    float e = __expf(logit - mx);
    float s = e;
#pragma unroll
    for (int o = 8; o; o >>= 1) s += __shfl_xor_sync(0xffffffffu, s, o, 16);
    float w = e / s;

    const float* offp = g_off + (size_t)m * Dd + h * (NLl * NPp * 2);
    const float* refp = ref + (size_t)m * (NLl * 2);

    float acc = 0.f;
#pragma unroll
    for (int l = 0; l < NLl; l++) {
        int Wl = c_lvl_W[l];
        float rx = refp[l * 2 + 0];
        float ry = refp[l * 2 + 1];
        const bf16* vbase = g_valbf + ((size_t)(b * NTOK + c_lvl_start[l])) * Dd + h * DHh + lane;
#pragma unroll
        for (int p = 0; p < NPp; p++) {
            float ox = offp[(l * NPp + p) * 2 + 0];
            float oy = offp[(l * NPp + p) * 2 + 1];
            float aw = __shfl_sync(0xffffffffu, w, l * NPp + p);
            float x = fmaf(rx, (float)Wl, ox) - 0.5f;
            float y = fmaf(ry, (float)Wl, oy) - 0.5f;
            float x0f = floorf(x), y0f = floorf(y);
            float fx = x - x0f, fy = y - y0f;
            int x0 = (int)x0f, y0 = (int)y0f;
            int x1 = x0 + 1, y1 = y0 + 1;
            bool vx0 = (x0 >= 0) & (x0 < Wl);
            bool vx1 = (x1 >= 0) & (x1 < Wl);
            bool vy0 = (y0 >= 0) & (y0 < Wl);
            bool vy1 = (y1 >= 0) & (y1 < Wl);
            if (vy0) {
                if (vx0) acc += aw * (1.f - fx) * (1.f - fy) *
                                __bfloat162float(vbase[(size_t)(y0 * Wl + x0) * Dd]);
                if (vx1) acc += aw * fx * (1.f - fy) *
                                __bfloat162float(vbase[(size_t)(y0 * Wl + x1) * Dd]);
            }
            if (vy1) {
                if (vx0) acc += aw * (1.f - fx) * fy *
                                __bfloat162float(vbase[(size_t)(y1 * Wl + x0) * Dd]);
                if (vx1) acc += aw * fx * fy *
                                __bfloat162float(vbase[(size_t)(y1 * Wl + x1) * Dd]);
            }
        }
    }
    bf16 hb, lb;
    splitf(acc, hb, lb);
    ah[(size_t)m * Dd + h * DHh + lane] = hb;
    al[(size_t)m * Dd + h * DHh + lane] = lb;
}

// ---------------- LayerNorm over D=256 ----------------
template <bool SP>
__global__ void ln_kernel(const float* __restrict__ in, const float* __restrict__ g,
                          const float* __restrict__ be, float* __restrict__ out,
                          bf16* __restrict__ oh, bf16* __restrict__ ol) {
    int m = blockIdx.x;
    int t = threadIdx.x;
    float v = in[(size_t)m * Dd + t];
    float s = v, sq = v * v;
#pragma unroll
    for (int o = 16; o; o >>= 1) {
        s += __shfl_xor_sync(0xffffffffu, s, o);
        sq += __shfl_xor_sync(0xffffffffu, sq, o);
    }
    __shared__ float ss[8], ssq[8];
    __shared__ float s_mean, s_rstd;
    if ((t & 31) == 0) { ss[t >> 5] = s; ssq[t >> 5] = sq; }
    __syncthreads();
    if (t == 0) {
        float ts = 0.f, tsq = 0.f;
#pragma unroll
        for (int i = 0; i < 8; i++) { ts += ss[i]; tsq += ssq[i]; }
        float mean = ts * (1.f / Dd);
        float var = tsq * (1.f / Dd) - mean * mean;
        s_mean = mean;
        s_rstd = rsqrtf(var + 1e-5f);
    }
    __syncthreads();
    float o = (v - s_mean) * s_rstd * g[t] + be[t];
    out[(size_t)m * Dd + t] = o;
    if (SP) {
        bf16 hb, lb;
        splitf(o, hb, lb);
        oh[(size_t)m * Dd + t] = hb;
        ol[(size_t)m * Dd + t] = lb;
    }
}

// ---------------- launch ----------------
extern "C" void kernel_launch(void* const* d_in, const int* in_sizes, int n_in,
                              void* d_out, int out_size) {
    const float* src   = (const float*)d_in[0];
    const float* pos   = (const float*)d_in[1];
    const float* ref   = (const float*)d_in[2];
    const float* w_val = (const float*)d_in[3];
    const float* b_val = (const float*)d_in[4];
    const float* w_off = (const float*)d_in[5];
    const float* b_off = (const float*)d_in[6];
    const float* w_att = (const float*)d_in[7];
    const float* b_att = (const float*)d_in[8];
    const float* w_out = (const float*)d_in[9];
    const float* b_out = (const float*)d_in[10];
    const float* g1    = (const float*)d_in[11];
    const float* be1   = (const float*)d_in[12];
    const float* w1    = (const float*)d_in[13];
    const float* b1    = (const float*)d_in[14];
    const float* w2    = (const float*)d_in[15];
    const float* b2    = (const float*)d_in[16];
    const float* g2    = (const float*)d_in[17];
    const float* be2   = (const float*)d_in[18];
    const unsigned char* mask = (const unsigned char*)d_in[21];

    bf16 *srch, *srcl, *qh, *ql, *ah, *al, *xh, *xl, *hh, *hl, *valbf;
    bf16 *wvh, *wvl, *wch, *wcl, *woh, *wol, *w1h, *w1l, *w2h, *w2l;
    float *p_off, *p_attn, *p_t1, *p_x, *p_t2, *p_bcomb;
    cudaGetSymbolAddress((void**)&srch, g_srch);  cudaGetSymbolAddress((void**)&srcl, g_srcl);
    cudaGetSymbolAddress((void**)&qh, g_qh);      cudaGetSymbolAddress((void**)&ql, g_ql);
    cudaGetSymbolAddress((void**)&ah, g_ah);      cudaGetSymbolAddress((void**)&al, g_al);
    cudaGetSymbolAddress((void**)&xh, g_xh);      cudaGetSymbolAddress((void**)&xl, g_xl);
    cudaGetSymbolAddress((void**)&hh, g_hh);      cudaGetSymbolAddress((void**)&hl, g_hl);
    cudaGetSymbolAddress((void**)&valbf, g_valbf);
    cudaGetSymbolAddress((void**)&wvh, g_wvh);    cudaGetSymbolAddress((void**)&wvl, g_wvl);
    cudaGetSymbolAddress((void**)&wch, g_wch);    cudaGetSymbolAddress((void**)&wcl, g_wcl);
    cudaGetSymbolAddress((void**)&woh, g_woh);    cudaGetSymbolAddress((void**)&wol, g_wol);
    cudaGetSymbolAddress((void**)&w1h, g_w1h);    cudaGetSymbolAddress((void**)&w1l, g_w1l);
    cudaGetSymbolAddress((void**)&w2h, g_w2h);    cudaGetSymbolAddress((void**)&w2l, g_w2l);
    cudaGetSymbolAddress((void**)&p_off, g_off);
    cudaGetSymbolAddress((void**)&p_attn, g_attn);
    cudaGetSymbolAddress((void**)&p_t1, g_t1);
    cudaGetSymbolAddress((void**)&p_x, g_x);
    cudaGetSymbolAddress((void**)&p_t2, g_t2);
    cudaGetSymbolAddress((void**)&p_bcomb, g_bcomb);

    const int M = Mrows;
    const int SMEM = NSTAGE * STAGEB;   // 122880
    cudaFuncSetAttribute(tc_gemm<E_MASK_BF16>, cudaFuncAttributeMaxDynamicSharedMemorySize, SMEM);
    cudaFuncSetAttribute(tc_gemm<E_OFFATTN>,   cudaFuncAttributeMaxDynamicSharedMemorySize, SMEM);
    cudaFuncSetAttribute(tc_gemm<E_ADD>,       cudaFuncAttributeMaxDynamicSharedMemorySize, SMEM);
    cudaFuncSetAttribute(tc_gemm<E_RELU_SPLIT>,cudaFuncAttributeMaxDynamicSharedMemorySize, SMEM);

    // prep: splits + packing
    src_q_split<<<(M * Dd / 4) / 256, 256>>>(src, pos, srch, srcl, qh, ql);
    WSplitArgs wa;
    wa.s[0] = w_val; wa.h[0] = wvh;         wa.l[0] = wvl;         wa.n4[0] = Dd * Dd / 4;
    wa.s[1] = w_off; wa.h[1] = wch;         wa.l[1] = wcl;         wa.n4[1] = Dd * Dd / 4;
    wa.s[2] = w_att; wa.h[2] = wch + 256 * Dd; wa.l[2] = wcl + 256 * Dd; wa.n4[2] = 128 * Dd / 4;
    wa.s[3] = w_out; wa.h[3] = woh;         wa.l[3] = wol;         wa.n4[3] = Dd * Dd / 4;
    wa.s[4] = w1;    wa.h[4] = w1h;         wa.l[4] = w1l;         wa.n4[4] = FFd * Dd / 4;
    wa.s[5] = w2;    wa.h[5] = w2h;         wa.l[5] = w2l;         wa.n4[5] = Dd * FFd / 4;
    wsplit_all<<<dim3(256, 6), 256>>>(wa);
    pack_bias<<<1, 384>>>(b_off, b_att, p_bcomb);

    // value = mask(src @ Wv^T + b) -> bf16
    tc_gemm<E_MASK_BF16><<<dim3(2, M / 128), 256, SMEM>>>(
        srch, srcl, wvh, wvl, b_val, nullptr, nullptr, valbf, nullptr,
        M, Dd, Dd, nullptr, mask);
    // [off ; attn-logits] = q @ [Woff;Wattn]^T + b
    tc_gemm<E_OFFATTN><<<dim3(3, M / 128), 256, SMEM>>>(
        qh, ql, wch, wcl, p_bcomb, p_off, p_attn, nullptr, nullptr,
        M, 384, Dd, nullptr, nullptr);
    // msdeform (softmax fused) -> split bf16 a
    sample_kernel<<<M, 256>>>(ref, ah, al);
    // t1 = src + a @ Wout^T + b
    tc_gemm<E_ADD><<<dim3(2, M / 128), 256, SMEM>>>(
        ah, al, woh, wol, b_out, p_t1, nullptr, nullptr, nullptr,
        M, Dd, Dd, src, nullptr);
    // x = LN(t1) (+ split)
    ln_kernel<true><<<M, 256>>>(p_t1, g1, be1, p_x, xh, xl);
    // h = relu(x @ W1^T + b1) -> split bf16
    tc_gemm<E_RELU_SPLIT><<<dim3(FFd / 128, M / 128), 256, SMEM>>>(
        xh, xl, w1h, w1l, b1, nullptr, nullptr, hh, hl,
        M, FFd, Dd, nullptr, nullptr);
    // t2 = x + h @ W2^T + b2
    tc_gemm<E_ADD><<<dim3(2, M / 128), 256, SMEM>>>(
        hh, hl, w2h, w2l, b2, p_t2, nullptr, nullptr, nullptr,
        M, Dd, FFd, p_x, nullptr);
    // out = LN(t2)
    ln_kernel<false><<<M, 256>>>(p_t2, g2, be2, (float*)d_out, nullptr, nullptr);
}

// round 5
// speedup vs baseline: 2.4764x; 1.3062x over previous
#include <cuda_runtime.h>
#include <cuda_bf16.h>
#include <math.h>
#include <stdint.h>

typedef __nv_bfloat16 bf16;

// ---------------- problem constants ----------------
#define Bb 4
#define NTOK 5440
#define Mrows (Bb * NTOK)   // 21760
#define Dd 256
#define FFd 1024
#define NHh 8
#define NLl 4
#define NPp 4
#define DHh 32

__device__ __constant__ int c_lvl_W[4]     = {64, 32, 16, 8};
__device__ __constant__ int c_lvl_start[4] = {0, 4096, 5120, 5376};

// ---------------- scratch (device globals) ----------------
// GEMM operands live in chunk-blocked swizzled layout (see blk_off).
__device__ bf16  g_srch[Mrows * Dd], g_srcl[Mrows * Dd];
__device__ bf16  g_qh  [Mrows * Dd], g_ql  [Mrows * Dd];
__device__ bf16  g_ah  [Mrows * Dd], g_al  [Mrows * Dd];
__device__ bf16  g_xh  [Mrows * Dd], g_xl  [Mrows * Dd];
__device__ bf16  g_hh  [Mrows * FFd], g_hl [Mrows * FFd];
__device__ bf16  g_valbf[Mrows * Dd];          // value bf16, plain row-major (sampler)
__device__ float g_off  [Mrows * Dd];
__device__ float g_attn [Mrows * 128];
__device__ float g_t1   [Mrows * Dd];
__device__ float g_x    [Mrows * Dd];
__device__ float g_t2   [Mrows * Dd];
// split weights (blocked layout over their row dim)
__device__ bf16 g_wvh[Dd*Dd],    g_wvl[Dd*Dd];
__device__ bf16 g_wch[384*Dd],   g_wcl[384*Dd];   // [w_off ; w_attn]
__device__ bf16 g_woh[Dd*Dd],    g_wol[Dd*Dd];
__device__ bf16 g_w1h[FFd*Dd],   g_w1l[FFd*Dd];
__device__ bf16 g_w2h[Dd*FFd],   g_w2l[Dd*FFd];
__device__ float g_bcomb[384];

// ---------------- blocked layout ----------------
// matrix [R, K] row-major logically; physical: panel p=row/128, chunk c=k/32,
// 8KB block per (p,c), within-block byte o = (row%128)*64 + (k%32)*2, SW128-swizzled.
__device__ __forceinline__ size_t blk_off(int row, int k, int K) {
    uint32_t o = (uint32_t)(row & 127) * 64 + (uint32_t)(k & 31) * 2;
    o = o ^ ((o >> 3) & 0x70);
    return ((size_t)((row >> 7) * (K >> 5) + (k >> 5)) << 13) + o;
}
#define SWZ(o) ((o) ^ (((o) >> 3) & 0x70))

// ---------------- PTX helpers ----------------
__device__ __forceinline__ uint32_t smem_u32(const void* p) {
    uint32_t a;
    asm("{ .reg .u64 t; cvta.to.shared.u64 t, %1; cvt.u32.u64 %0, t; }" : "=r"(a) : "l"(p));
    return a;
}
#define MBAR_INIT(addr, cnt) \
    asm volatile("mbarrier.init.shared.b64 [%0], %1;" :: "r"((uint32_t)(addr)), "r"((uint32_t)(cnt)) : "memory")
#define MBAR_ARRIVE(addr) \
    asm volatile("mbarrier.arrive.shared.b64 _, [%0];" :: "r"((uint32_t)(addr)) : "memory")
#define MBAR_EXPECT_TX(addr, tx) \
    asm volatile("mbarrier.arrive.expect_tx.shared.b64 _, [%0], %1;" :: "r"((uint32_t)(addr)), "r"((uint32_t)(tx)) : "memory")
#define BULK_G2S(dst, src, bytes, mbar) \
    asm volatile("cp.async.bulk.shared::cluster.global.mbarrier::complete_tx::bytes [%0], [%1], %2, [%3];" \
        :: "r"((uint32_t)(dst)), "l"(src), "r"((uint32_t)(bytes)), "r"((uint32_t)(mbar)) : "memory")
#define FENCE_ASYNC() asm volatile("fence.proxy.async.shared::cta;" ::: "memory")

#define MBAR_WAIT(addr, par) do { \
    uint32_t _m = (uint32_t)(addr); uint32_t _p = (uint32_t)(par); uint32_t _d; \
    asm volatile("{\n\t.reg .pred p;\n\t" \
        "mbarrier.try_wait.parity.acquire.cta.shared::cta.b64 p, [%1], %2;\n\t" \
        "selp.b32 %0, 1, 0, p;\n\t}" : "=r"(_d) : "r"(_m), "r"(_p) : "memory"); \
    if (!_d) { \
        asm volatile("{\n\t.reg .pred P1;\n\t" \
            "WL_%=:\n\t" \
            "mbarrier.try_wait.parity.acquire.cta.shared::cta.b64 P1, [%0], %1, 0x989680;\n\t" \
            "@P1 bra.uni WD_%=;\n\t" \
            "bra.uni WL_%=;\n\t" \
            "WD_%=:\n\t}" :: "r"(_m), "r"(_p) : "memory"); \
    } } while (0)

__device__ __forceinline__ void ldsm4(uint32_t* r, uint32_t a) {
    asm volatile("ldmatrix.sync.aligned.m8n8.x4.shared.b16 {%0,%1,%2,%3}, [%4];"
        : "=r"(r[0]), "=r"(r[1]), "=r"(r[2]), "=r"(r[3]) : "r"(a));
}
__device__ __forceinline__ void mma16816(float* d, const uint32_t* a, const uint32_t* b) {
    asm volatile("mma.sync.aligned.m16n8k16.row.col.f32.bf16.bf16.f32 "
        "{%0,%1,%2,%3}, {%4,%5,%6,%7}, {%8,%9}, {%0,%1,%2,%3};"
        : "+f"(d[0]), "+f"(d[1]), "+f"(d[2]), "+f"(d[3])
        : "r"(a[0]), "r"(a[1]), "r"(a[2]), "r"(a[3]), "r"(b[0]), "r"(b[1]));
}

__device__ __forceinline__ void splitf(float v, bf16& h, bf16& l) {
    h = __float2bfloat16(v);
    l = __float2bfloat16(v - __bfloat162float(h));
}
__device__ __forceinline__ void split4(float4 v, uint2& hi, uint2& lo) {
    bf16 h0, l0, h1, l1, h2, l2, h3, l3;
    splitf(v.x, h0, l0); splitf(v.y, h1, l1);
    splitf(v.z, h2, l2); splitf(v.w, h3, l3);
    __nv_bfloat162 a, b;
    a.x = h0; a.y = h1; b.x = h2; b.y = h3;
    hi.x = *(uint32_t*)&a; hi.y = *(uint32_t*)&b;
    a.x = l0; a.y = l1; b.x = l2; b.y = l3;
    lo.x = *(uint32_t*)&a; lo.y = *(uint32_t*)&b;
}
__device__ __forceinline__ void split2(float x, float y, uint32_t& hi, uint32_t& lo) {
    bf16 hx, lx, hy, ly;
    splitf(x, hx, lx); splitf(y, hy, ly);
    __nv_bfloat162 a;
    a.x = hx; a.y = hy; hi = *(uint32_t*)&a;
    a.x = lx; a.y = ly; lo = *(uint32_t*)&a;
}

// ---------------- prep kernels (write blocked layout) ----------------
__global__ void src_q_split(const float* __restrict__ src, const float* __restrict__ pos,
                            bf16* __restrict__ sh, bf16* __restrict__ sl,
                            bf16* __restrict__ qh, bf16* __restrict__ ql) {
    int i = blockIdx.x * blockDim.x + threadIdx.x;      // float4 index
    int e = i * 4;
    int m = e >> 8, k = e & 255;
    size_t off = blk_off(m, k, 256);
    float4 s = ((const float4*)src)[i];
    float4 p = ((const float4*)pos)[i];
    uint2 hi, lo;
    split4(s, hi, lo);
    *(uint2*)((char*)sh + off) = hi;
    *(uint2*)((char*)sl + off) = lo;
    float4 q = make_float4(s.x + p.x, s.y + p.y, s.z + p.z, s.w + p.w);
    split4(q, hi, lo);
    *(uint2*)((char*)qh + off) = hi;
    *(uint2*)((char*)ql + off) = lo;
}

struct WSplitArgs {
    const float* s[6];
    bf16* h[6];
    bf16* l[6];
    int n4[6];
    int kshift[6];   // log2(K)
    int rowoff[6];
};
__global__ void wsplit_all(WSplitArgs a) {
    int seg = blockIdx.y;
    int i = blockIdx.x * blockDim.x + threadIdx.x;
    if (i >= a.n4[seg]) return;
    int ks = a.kshift[seg];
    int K = 1 << ks;
    int e = i * 4;
    int m = (e >> ks) + a.rowoff[seg];
    int k = e & (K - 1);
    size_t off = blk_off(m, k, K);
    uint2 hi, lo;
    split4(((const float4*)a.s[seg])[i], hi, lo);
    *(uint2*)((char*)a.h[seg] + off) = hi;
    *(uint2*)((char*)a.l[seg] + off) = lo;
}

__global__ void pack_bias(const float* __restrict__ bo, const float* __restrict__ ba,
                          float* __restrict__ dst) {
    int i = threadIdx.x;
    dst[i] = (i < 256) ? bo[i] : ba[i - 256];
}

// ---------------- bulk-copy HMMA GEMM ----------------
// C[M,N] = (Ah+Al)(Bh+Bl)^T 3-term split. CTA 128x128, chunk 32, 256 threads.
// Operands in blocked layout: per (panel, chunk) one contiguous 8KB swizzled block.
// 3-stage pipeline fed by cp.async.bulk (4 x 8KB per chunk), mbarrier sync.
#define CHB    8192
#define STGB   (4 * CHB)
#define NST    3
#define SMEM_GEMM (128 + NST * STGB)

enum { E_MASK_BF16 = 0, E_OFFATTN = 1, E_ADD = 2, E_RELU_SPLIT = 3 };

template <int EPI>
__global__ __launch_bounds__(256, 2)
void tc_gemm(const bf16* __restrict__ Ah, const bf16* __restrict__ Al,
             const bf16* __restrict__ Bh, const bf16* __restrict__ Bl,
             const float* __restrict__ bias,
             float* __restrict__ outF, float* __restrict__ outF2,
             bf16* __restrict__ outBFh, bf16* __restrict__ outBFl,
             int M, int N, int K,
             const float* __restrict__ add, const unsigned char* __restrict__ mask) {
    extern __shared__ char sm[];
    const uint32_t smb = smem_u32(sm);
    // barriers: full[s] at smb + s*16, empty[s] at smb + 48 + s*16
    const uint32_t fullb = smb, emptyb = smb + 48;
    const uint32_t stg0 = smb + 128;

    const int tid = threadIdx.x;
    const int wid = tid >> 5, lane = tid & 31;
    const int wm = wid & 1, wn = wid >> 1;
    const int g = lane >> 2, t = lane & 3;
    const int bm = blockIdx.y * 128;
    const int bn = blockIdx.x * 128;
    const int pA = bm >> 7, pB = bn >> 7;
    const int nchunks = K >> 5;

    if (tid == 0) {
#pragma unroll
        for (int s = 0; s < NST; s++) {
            MBAR_INIT(fullb + s * 16, 1);
            MBAR_INIT(emptyb + s * 16, 8);
        }
        FENCE_ASYNC();
    }
    __syncthreads();

    const char* Ahc = (const char*)Ah + (size_t)pA * nchunks * CHB;
    const char* Alc = (const char*)Al + (size_t)pA * nchunks * CHB;
    const char* Bhc = (const char*)Bh + (size_t)pB * nchunks * CHB;
    const char* Blc = (const char*)Bl + (size_t)pB * nchunks * CHB;

    auto issue = [&](int c) {
        int s = c % NST;
        uint32_t dst = stg0 + s * STGB;
        uint32_t mb = fullb + s * 16;
        MBAR_EXPECT_TX(mb, STGB);
        size_t co = (size_t)c * CHB;
        BULK_G2S(dst,           Ahc + co, CHB, mb);
        BULK_G2S(dst + CHB,     Alc + co, CHB, mb);
        BULK_G2S(dst + 2 * CHB, Bhc + co, CHB, mb);
        BULK_G2S(dst + 3 * CHB, Blc + co, CHB, mb);
    };

    if (tid == 0) {
        int pre = nchunks < NST ? nchunks : NST;
        for (int c = 0; c < pre; c++) issue(c);
    }

    float acc[4][4][4];
#pragma unroll
    for (int i = 0; i < 4; i++)
#pragma unroll
        for (int j = 0; j < 4; j++)
#pragma unroll
            for (int r = 0; r < 4; r++) acc[i][j][r] = 0.f;

    // per-lane row/byte components for ldmatrix (within 8KB chunk block)
    const uint32_t rA = (uint32_t)(lane & 15);             // + wm*64 + i*16
    const uint32_t qA = (uint32_t)(lane >> 4) * 16;        // + ks*32
    const uint32_t rB = (uint32_t)(((lane >> 4) & 1) * 8 + (lane & 7));
    const uint32_t qB = (uint32_t)((lane >> 3) & 1) * 16;

    for (int c = 0; c < nchunks; c++) {
        const int s = c % NST;
        const int u = c / NST;
        MBAR_WAIT(fullb + s * 16, u & 1);

        const uint32_t st = stg0 + s * STGB;
#pragma unroll
        for (int ks = 0; ks < 2; ks++) {
            uint32_t Ahf[4][4], Alf[4][4], Bhf[2][4], Blf[2][4];
#pragma unroll
            for (int i = 0; i < 4; i++) {
                uint32_t o = (wm * 64 + i * 16 + rA) * 64 + qA + ks * 32;
                o = SWZ(o);
                ldsm4(Ahf[i], st + o);
                ldsm4(Alf[i], st + CHB + o);
            }
#pragma unroll
            for (int p = 0; p < 2; p++) {
                uint32_t o = (wn * 32 + p * 16 + rB) * 64 + qB + ks * 32;
                o = SWZ(o);
                ldsm4(Bhf[p], st + 2 * CHB + o);
                ldsm4(Blf[p], st + 3 * CHB + o);
            }
#pragma unroll
            for (int i = 0; i < 4; i++)
#pragma unroll
                for (int j = 0; j < 4; j++) {
                    const uint32_t* bh = &Bhf[j >> 1][(j & 1) * 2];
                    const uint32_t* bl = &Blf[j >> 1][(j & 1) * 2];
                    mma16816(acc[i][j], Ahf[i], bh);
                    mma16816(acc[i][j], Alf[i], bh);
                    mma16816(acc[i][j], Ahf[i], bl);
                }
        }
        __syncwarp();
        if (lane == 0) MBAR_ARRIVE(emptyb + s * 16);
        if (tid == 0 && c + NST < nchunks) {
            MBAR_WAIT(emptyb + s * 16, u & 1);
            issue(c + NST);
        }
    }

    // ---------------- epilogue ----------------
#pragma unroll
    for (int i = 0; i < 4; i++) {
        int row0 = bm + wm * 64 + i * 16 + g;
#pragma unroll
        for (int j = 0; j < 4; j++) {
            int col = bn + wn * 32 + j * 8 + 2 * t;
            float b0 = bias[col], b1 = bias[col + 1];
#pragma unroll
            for (int half = 0; half < 2; half++) {
                int row = row0 + half * 8;
                float v0 = acc[i][j][half * 2 + 0] + b0;
                float v1 = acc[i][j][half * 2 + 1] + b1;
                if (EPI == E_MASK_BF16) {
                    if (mask[row]) { v0 = 0.f; v1 = 0.f; }
                    __nv_bfloat162 pk;
                    pk.x = __float2bfloat16(v0); pk.y = __float2bfloat16(v1);
                    *(uint32_t*)(outBFh + (size_t)row * N + col) = *(uint32_t*)&pk;
                } else if (EPI == E_OFFATTN) {
                    if (bn == 256)
                        *(float2*)(outF2 + (size_t)row * 128 + (col - 256)) = make_float2(v0, v1);
                    else
                        *(float2*)(outF + (size_t)row * 256 + col) = make_float2(v0, v1);
                } else if (EPI == E_ADD) {
                    float2 r2 = *(const float2*)(add + (size_t)row * N + col);
                    *(float2*)(outF + (size_t)row * N + col) = make_float2(v0 + r2.x, v1 + r2.y);
                } else if (EPI == E_RELU_SPLIT) {
                    v0 = fmaxf(v0, 0.f); v1 = fmaxf(v1, 0.f);
                    uint32_t hi, lo;
                    split2(v0, v1, hi, lo);
                    size_t off = blk_off(row, col, N);
                    *(uint32_t*)((char*)outBFh + off) = hi;
                    *(uint32_t*)((char*)outBFl + off) = lo;
                }
            }
        }
    }
}

// ---------------- msdeform sampling (softmax fused; writes blocked split bf16) ----------------
__global__ void sample_kernel(const float* __restrict__ ref,
                              bf16* __restrict__ ah, bf16* __restrict__ al) {
    int m = blockIdx.x;
    int b = m / NTOK;
    int h = threadIdx.x >> 5;
    int lane = threadIdx.x & 31;

    const float* logp = g_attn + (size_t)m * 128 + h * 16;
    float logit = (lane < 16) ? logp[lane] : -1e30f;
    float mx = logit;
#pragma unroll
    for (int o = 8; o; o >>= 1) mx = fmaxf(mx, __shfl_xor_sync(0xffffffffu, mx, o, 16));
    float e = __expf(logit - mx);
    float s = e;
#pragma unroll
    for (int o = 8; o; o >>= 1) s += __shfl_xor_sync(0xffffffffu, s, o, 16);
    float w = e / s;

    const float* offp = g_off + (size_t)m * Dd + h * (NLl * NPp * 2);
    const float* refp = ref + (size_t)m * (NLl * 2);

    float acc = 0.f;
#pragma unroll
    for (int l = 0; l < NLl; l++) {
        int Wl = c_lvl_W[l];
        float rx = refp[l * 2 + 0];
        float ry = refp[l * 2 + 1];
        const bf16* vbase = g_valbf + ((size_t)(b * NTOK + c_lvl_start[l])) * Dd + h * DHh + lane;
#pragma unroll
        for (int p = 0; p < NPp; p++) {
            float ox = offp[(l * NPp + p) * 2 + 0];
            float oy = offp[(l * NPp + p) * 2 + 1];
            float aw = __shfl_sync(0xffffffffu, w, l * NPp + p);
            float x = fmaf(rx, (float)Wl, ox) - 0.5f;
            float y = fmaf(ry, (float)Wl, oy) - 0.5f;
            float x0f = floorf(x), y0f = floorf(y);
            float fx = x - x0f, fy = y - y0f;
            int x0 = (int)x0f, y0 = (int)y0f;
            int x1 = x0 + 1, y1 = y0 + 1;
            bool vx0 = (x0 >= 0) & (x0 < Wl);
            bool vx1 = (x1 >= 0) & (x1 < Wl);
            bool vy0 = (y0 >= 0) & (y0 < Wl);
            bool vy1 = (y1 >= 0) & (y1 < Wl);
            if (vy0) {
                if (vx0) acc += aw * (1.f - fx) * (1.f - fy) *
                                __bfloat162float(vbase[(size_t)(y0 * Wl + x0) * Dd]);
                if (vx1) acc += aw * fx * (1.f - fy) *
                                __bfloat162float(vbase[(size_t)(y0 * Wl + x1) * Dd]);
            }
            if (vy1) {
                if (vx0) acc += aw * (1.f - fx) * fy *
                                __bfloat162float(vbase[(size_t)(y1 * Wl + x0) * Dd]);
                if (vx1) acc += aw * fx * fy *
                                __bfloat162float(vbase[(size_t)(y1 * Wl + x1) * Dd]);
            }
        }
    }
    bf16 hb, lb;
    splitf(acc, hb, lb);
    size_t off = blk_off(m, h * DHh + lane, 256);
    *(bf16*)((char*)ah + off) = hb;
    *(bf16*)((char*)al + off) = lb;
}

// ---------------- LayerNorm over D=256 ----------------
template <bool SP>
__global__ void ln_kernel(const float* __restrict__ in, const float* __restrict__ g,
                          const float* __restrict__ be, float* __restrict__ out,
                          bf16* __restrict__ oh, bf16* __restrict__ ol) {
    int m = blockIdx.x;
    int t = threadIdx.x;
    float v = in[(size_t)m * Dd + t];
    float s = v, sq = v * v;
#pragma unroll
    for (int o = 16; o; o >>= 1) {
        s += __shfl_xor_sync(0xffffffffu, s, o);
        sq += __shfl_xor_sync(0xffffffffu, sq, o);
    }
    __shared__ float ss[8], ssq[8];
    __shared__ float s_mean, s_rstd;
    if ((t & 31) == 0) { ss[t >> 5] = s; ssq[t >> 5] = sq; }
    __syncthreads();
    if (t == 0) {
        float ts = 0.f, tsq = 0.f;
#pragma unroll
        for (int i = 0; i < 8; i++) { ts += ss[i]; tsq += ssq[i]; }
        float mean = ts * (1.f / Dd);
        float var = tsq * (1.f / Dd) - mean * mean;
        s_mean = mean;
        s_rstd = rsqrtf(var + 1e-5f);
    }
    __syncthreads();
    float o = (v - s_mean) * s_rstd * g[t] + be[t];
    out[(size_t)m * Dd + t] = o;
    if (SP) {
        bf16 hb, lb;
        splitf(o, hb, lb);
        size_t off = blk_off(m, t, 256);
        *(bf16*)((char*)oh + off) = hb;
        *(bf16*)((char*)ol + off) = lb;
    }
}

// ---------------- launch ----------------
extern "C" void kernel_launch(void* const* d_in, const int* in_sizes, int n_in,
                              void* d_out, int out_size) {
    const float* src   = (const float*)d_in[0];
    const float* pos   = (const float*)d_in[1];
    const float* ref   = (const float*)d_in[2];
    const float* w_val = (const float*)d_in[3];
    const float* b_val = (const float*)d_in[4];
    const float* w_off = (const float*)d_in[5];
    const float* b_off = (const float*)d_in[6];
    const float* w_att = (const float*)d_in[7];
    const float* b_att = (const float*)d_in[8];
    const float* w_out = (const float*)d_in[9];
    const float* b_out = (const float*)d_in[10];
    const float* g1    = (const float*)d_in[11];
    const float* be1   = (const float*)d_in[12];
    const float* w1    = (const float*)d_in[13];
    const float* b1    = (const float*)d_in[14];
    const float* w2    = (const float*)d_in[15];
    const float* b2    = (const float*)d_in[16];
    const float* g2    = (const float*)d_in[17];
    const float* be2   = (const float*)d_in[18];
    const unsigned char* mask = (const unsigned char*)d_in[21];

    bf16 *srch, *srcl, *qh, *ql, *ah, *al, *xh, *xl, *hh, *hl, *valbf;
    bf16 *wvh, *wvl, *wch, *wcl, *woh, *wol, *w1h, *w1l, *w2h, *w2l;
    float *p_off, *p_attn, *p_t1, *p_x, *p_t2, *p_bcomb;
    cudaGetSymbolAddress((void**)&srch, g_srch);  cudaGetSymbolAddress((void**)&srcl, g_srcl);
    cudaGetSymbolAddress((void**)&qh, g_qh);      cudaGetSymbolAddress((void**)&ql, g_ql);
    cudaGetSymbolAddress((void**)&ah, g_ah);      cudaGetSymbolAddress((void**)&al, g_al);
    cudaGetSymbolAddress((void**)&xh, g_xh);      cudaGetSymbolAddress((void**)&xl, g_xl);
    cudaGetSymbolAddress((void**)&hh, g_hh);      cudaGetSymbolAddress((void**)&hl, g_hl);
    cudaGetSymbolAddress((void**)&valbf, g_valbf);
    cudaGetSymbolAddress((void**)&wvh, g_wvh);    cudaGetSymbolAddress((void**)&wvl, g_wvl);
    cudaGetSymbolAddress((void**)&wch, g_wch);    cudaGetSymbolAddress((void**)&wcl, g_wcl);
    cudaGetSymbolAddress((void**)&woh, g_woh);    cudaGetSymbolAddress((void**)&wol, g_wol);
    cudaGetSymbolAddress((void**)&w1h, g_w1h);    cudaGetSymbolAddress((void**)&w1l, g_w1l);
    cudaGetSymbolAddress((void**)&w2h, g_w2h);    cudaGetSymbolAddress((void**)&w2l, g_w2l);
    cudaGetSymbolAddress((void**)&p_off, g_off);
    cudaGetSymbolAddress((void**)&p_attn, g_attn);
    cudaGetSymbolAddress((void**)&p_t1, g_t1);
    cudaGetSymbolAddress((void**)&p_x, g_x);
    cudaGetSymbolAddress((void**)&p_t2, g_t2);
    cudaGetSymbolAddress((void**)&p_bcomb, g_bcomb);

    const int M = Mrows;
    cudaFuncSetAttribute(tc_gemm<E_MASK_BF16>, cudaFuncAttributeMaxDynamicSharedMemorySize, SMEM_GEMM);
    cudaFuncSetAttribute(tc_gemm<E_OFFATTN>,   cudaFuncAttributeMaxDynamicSharedMemorySize, SMEM_GEMM);
    cudaFuncSetAttribute(tc_gemm<E_ADD>,       cudaFuncAttributeMaxDynamicSharedMemorySize, SMEM_GEMM);
    cudaFuncSetAttribute(tc_gemm<E_RELU_SPLIT>,cudaFuncAttributeMaxDynamicSharedMemorySize, SMEM_GEMM);

    // prep
    src_q_split<<<(M * Dd / 4) / 256, 256>>>(src, pos, srch, srcl, qh, ql);
    WSplitArgs wa;
    wa.s[0] = w_val; wa.h[0] = wvh; wa.l[0] = wvl; wa.n4[0] = Dd * Dd / 4;  wa.kshift[0] = 8;  wa.rowoff[0] = 0;
    wa.s[1] = w_off; wa.h[1] = wch; wa.l[1] = wcl; wa.n4[1] = Dd * Dd / 4;  wa.kshift[1] = 8;  wa.rowoff[1] = 0;
    wa.s[2] = w_att; wa.h[2] = wch; wa.l[2] = wcl; wa.n4[2] = 128 * Dd / 4; wa.kshift[2] = 8;  wa.rowoff[2] = 256;
    wa.s[3] = w_out; wa.h[3] = woh; wa.l[3] = wol; wa.n4[3] = Dd * Dd / 4;  wa.kshift[3] = 8;  wa.rowoff[3] = 0;
    wa.s[4] = w1;    wa.h[4] = w1h; wa.l[4] = w1l; wa.n4[4] = FFd * Dd / 4; wa.kshift[4] = 8;  wa.rowoff[4] = 0;
    wa.s[5] = w2;    wa.h[5] = w2h; wa.l[5] = w2l; wa.n4[5] = Dd * FFd / 4; wa.kshift[5] = 10; wa.rowoff[5] = 0;
    wsplit_all<<<dim3(256, 6), 256>>>(wa);
    pack_bias<<<1, 384>>>(b_off, b_att, p_bcomb);

    // value = mask(src @ Wv^T + b) -> bf16 row-major
    tc_gemm<E_MASK_BF16><<<dim3(2, M / 128), 256, SMEM_GEMM>>>(
        srch, srcl, wvh, wvl, b_val, nullptr, nullptr, valbf, nullptr,
        M, Dd, Dd, nullptr, mask);
    // [off ; attn-logits] = q @ [Woff;Wattn]^T + b
    tc_gemm<E_OFFATTN><<<dim3(3, M / 128), 256, SMEM_GEMM>>>(
        qh, ql, wch, wcl, p_bcomb, p_off, p_attn, nullptr, nullptr,
        M, 384, Dd, nullptr, nullptr);
    // msdeform (softmax fused) -> blocked split bf16 a
    sample_kernel<<<M, 256>>>(ref, ah, al);
    // t1 = src + a @ Wout^T + b
    tc_gemm<E_ADD><<<dim3(2, M / 128), 256, SMEM_GEMM>>>(
        ah, al, woh, wol, b_out, p_t1, nullptr, nullptr, nullptr,
        M, Dd, Dd, src, nullptr);
    // x = LN(t1) (+ blocked split)
    ln_kernel<true><<<M, 256>>>(p_t1, g1, be1, p_x, xh, xl);
    // h = relu(x @ W1^T + b1) -> blocked split bf16
    tc_gemm<E_RELU_SPLIT><<<dim3(FFd / 128, M / 128), 256, SMEM_GEMM>>>(
        xh, xl, w1h, w1l, b1, nullptr, nullptr, hh, hl,
        M, FFd, Dd, nullptr, nullptr);
    // t2 = x + h @ W2^T + b2
    tc_gemm<E_ADD><<<dim3(2, M / 128), 256, SMEM_GEMM>>>(
        hh, hl, w2h, w2l, b2, p_t2, nullptr, nullptr, nullptr,
        M, Dd, FFd, p_x, nullptr);
    // out = LN(t2)
    ln_kernel<false><<<M, 256>>>(p_t2, g2, be2, (float*)d_out, nullptr, nullptr);
}

// round 6
// speedup vs baseline: 2.8666x; 1.1576x over previous
#include <cuda_runtime.h>
#include <cuda_bf16.h>
#include <math.h>
#include <stdint.h>

typedef __nv_bfloat16 bf16;

// ---------------- problem constants ----------------
#define Bb 4
#define NTOK 5440
#define Mrows (Bb * NTOK)   // 21760
#define Dd 256
#define FFd 1024
#define NHh 8
#define NLl 4
#define NPp 4
#define DHh 32
#define GPERS 304           // persistent grid (2 per SM x 152 SMs)

__device__ __constant__ int c_lvl_W[4]     = {64, 32, 16, 8};
__device__ __constant__ int c_lvl_start[4] = {0, 4096, 5120, 5376};

// ---------------- scratch (device globals) ----------------
__device__ bf16  g_srch[Mrows * Dd], g_srcl[Mrows * Dd];
__device__ bf16  g_qh  [Mrows * Dd], g_ql  [Mrows * Dd];
__device__ bf16  g_ah  [Mrows * Dd], g_al  [Mrows * Dd];
__device__ bf16  g_xh  [Mrows * Dd], g_xl  [Mrows * Dd];
__device__ bf16  g_hh  [Mrows * FFd], g_hl [Mrows * FFd];
__device__ bf16  g_valbf[Mrows * Dd];
__device__ float g_off  [Mrows * Dd];
__device__ float g_attn [Mrows * 128];
__device__ float g_t1   [Mrows * Dd];
__device__ float g_x    [Mrows * Dd];
__device__ float g_t2   [Mrows * Dd];
__device__ bf16 g_wvh[Dd*Dd],    g_wvl[Dd*Dd];
__device__ bf16 g_wch[384*Dd],   g_wcl[384*Dd];
__device__ bf16 g_woh[Dd*Dd],    g_wol[Dd*Dd];
__device__ bf16 g_w1h[FFd*Dd],   g_w1l[FFd*Dd];
__device__ bf16 g_w2h[Dd*FFd],   g_w2l[Dd*FFd];
__device__ float g_bcomb[384];

// ---------------- blocked layout ----------------
__device__ __forceinline__ size_t blk_off(int row, int k, int K) {
    uint32_t o = (uint32_t)(row & 127) * 64 + (uint32_t)(k & 31) * 2;
    o = o ^ ((o >> 3) & 0x70);
    return ((size_t)((row >> 7) * (K >> 5) + (k >> 5)) << 13) + o;
}
#define SWZ(o) ((o) ^ (((o) >> 3) & 0x70))

// ---------------- PTX helpers ----------------
__device__ __forceinline__ uint32_t smem_u32(const void* p) {
    uint32_t a;
    asm("{ .reg .u64 t; cvta.to.shared.u64 t, %1; cvt.u32.u64 %0, t; }" : "=r"(a) : "l"(p));
    return a;
}
#define MBAR_INIT(addr, cnt) \
    asm volatile("mbarrier.init.shared.b64 [%0], %1;" :: "r"((uint32_t)(addr)), "r"((uint32_t)(cnt)) : "memory")
#define MBAR_ARRIVE(addr) \
    asm volatile("mbarrier.arrive.shared.b64 _, [%0];" :: "r"((uint32_t)(addr)) : "memory")
#define MBAR_EXPECT_TX(addr, tx) \
    asm volatile("mbarrier.arrive.expect_tx.shared.b64 _, [%0], %1;" :: "r"((uint32_t)(addr)), "r"((uint32_t)(tx)) : "memory")
#define BULK_G2S(dst, src, bytes, mbar) \
    asm volatile("cp.async.bulk.shared::cluster.global.mbarrier::complete_tx::bytes [%0], [%1], %2, [%3];" \
        :: "r"((uint32_t)(dst)), "l"(src), "r"((uint32_t)(bytes)), "r"((uint32_t)(mbar)) : "memory")
#define FENCE_ASYNC() asm volatile("fence.proxy.async.shared::cta;" ::: "memory")

#define MBAR_WAIT(addr, par) do { \
    uint32_t _m = (uint32_t)(addr); uint32_t _p = (uint32_t)(par); uint32_t _d; \
    asm volatile("{\n\t.reg .pred p;\n\t" \
        "mbarrier.try_wait.parity.acquire.cta.shared::cta.b64 p, [%1], %2;\n\t" \
        "selp.b32 %0, 1, 0, p;\n\t}" : "=r"(_d) : "r"(_m), "r"(_p) : "memory"); \
    if (!_d) { \
        asm volatile("{\n\t.reg .pred P1;\n\t" \
            "WL_%=:\n\t" \
            "mbarrier.try_wait.parity.acquire.cta.shared::cta.b64 P1, [%0], %1, 0x989680;\n\t" \
            "@P1 bra.uni WD_%=;\n\t" \
            "bra.uni WL_%=;\n\t" \
            "WD_%=:\n\t}" :: "r"(_m), "r"(_p) : "memory"); \
    } } while (0)

__device__ __forceinline__ void ldsm4(uint32_t* r, uint32_t a) {
    asm volatile("ldmatrix.sync.aligned.m8n8.x4.shared.b16 {%0,%1,%2,%3}, [%4];"
        : "=r"(r[0]), "=r"(r[1]), "=r"(r[2]), "=r"(r[3]) : "r"(a));
}
__device__ __forceinline__ void mma16816(float* d, const uint32_t* a, const uint32_t* b) {
    asm volatile("mma.sync.aligned.m16n8k16.row.col.f32.bf16.bf16.f32 "
        "{%0,%1,%2,%3}, {%4,%5,%6,%7}, {%8,%9}, {%0,%1,%2,%3};"
        : "+f"(d[0]), "+f"(d[1]), "+f"(d[2]), "+f"(d[3])
        : "r"(a[0]), "r"(a[1]), "r"(a[2]), "r"(a[3]), "r"(b[0]), "r"(b[1]));
}

__device__ __forceinline__ void splitf(float v, bf16& h, bf16& l) {
    h = __float2bfloat16(v);
    l = __float2bfloat16(v - __bfloat162float(h));
}
__device__ __forceinline__ void split4(float4 v, uint2& hi, uint2& lo) {
    bf16 h0, l0, h1, l1, h2, l2, h3, l3;
    splitf(v.x, h0, l0); splitf(v.y, h1, l1);
    splitf(v.z, h2, l2); splitf(v.w, h3, l3);
    __nv_bfloat162 a, b;
    a.x = h0; a.y = h1; b.x = h2; b.y = h3;
    hi.x = *(uint32_t*)&a; hi.y = *(uint32_t*)&b;
    a.x = l0; a.y = l1; b.x = l2; b.y = l3;
    lo.x = *(uint32_t*)&a; lo.y = *(uint32_t*)&b;
}
__device__ __forceinline__ void split2(float x, float y, uint32_t& hi, uint32_t& lo) {
    bf16 hx, lx, hy, ly;
    splitf(x, hx, lx); splitf(y, hy, ly);
    __nv_bfloat162 a;
    a.x = hx; a.y = hy; hi = *(uint32_t*)&a;
    a.x = lx; a.y = ly; lo = *(uint32_t*)&a;
}

// ---------------- prep kernels ----------------
__global__ void src_q_split(const float* __restrict__ src, const float* __restrict__ pos,
                            bf16* __restrict__ sh, bf16* __restrict__ sl,
                            bf16* __restrict__ qh, bf16* __restrict__ ql) {
    int i = blockIdx.x * blockDim.x + threadIdx.x;
    int e = i * 4;
    int m = e >> 8, k = e & 255;
    size_t off = blk_off(m, k, 256);
    float4 s = ((const float4*)src)[i];
    float4 p = ((const float4*)pos)[i];
    uint2 hi, lo;
    split4(s, hi, lo);
    *(uint2*)((char*)sh + off) = hi;
    *(uint2*)((char*)sl + off) = lo;
    float4 q = make_float4(s.x + p.x, s.y + p.y, s.z + p.z, s.w + p.w);
    split4(q, hi, lo);
    *(uint2*)((char*)qh + off) = hi;
    *(uint2*)((char*)ql + off) = lo;
}

struct WSplitArgs {
    const float* s[6];
    bf16* h[6];
    bf16* l[6];
    int n4[6];
    int kshift[6];
    int rowoff[6];
};
__global__ void wsplit_all(WSplitArgs a) {
    int seg = blockIdx.y;
    int i = blockIdx.x * blockDim.x + threadIdx.x;
    if (i >= a.n4[seg]) return;
    int ks = a.kshift[seg];
    int K = 1 << ks;
    int e = i * 4;
    int m = (e >> ks) + a.rowoff[seg];
    int k = e & (K - 1);
    size_t off = blk_off(m, k, K);
    uint2 hi, lo;
    split4(((const float4*)a.s[seg])[i], hi, lo);
    *(uint2*)((char*)a.h[seg] + off) = hi;
    *(uint2*)((char*)a.l[seg] + off) = lo;
}

__global__ void pack_bias(const float* __restrict__ bo, const float* __restrict__ ba,
                          float* __restrict__ dst) {
    int i = threadIdx.x;
    dst[i] = (i < 256) ? bo[i] : ba[i - 256];
}

// ---------------- persistent bulk-copy HMMA GEMM ----------------
// C = (Ah+Al)(Bh+Bl)^T 3-term split. M-tile 128, N-tile NT (64 or 128), chunk 32.
// Flat job list (m, n, kt) over persistent grid; 3-stage bulk-copy pipeline.
#define NST 3
enum { E_MASK_BF16 = 0, E_OFFATTN = 1, E_ADD = 2, E_RELU_SPLIT = 3, E_ATOMIC = 4 };

template <int NT, int EPI>
__global__ __launch_bounds__(256, 2)
void tc_gemm(const bf16* __restrict__ Ah, const bf16* __restrict__ Al,
             const bf16* __restrict__ Bh, const bf16* __restrict__ Bl,
             const float* __restrict__ bias,
             float* __restrict__ outF, float* __restrict__ outF2,
             bf16* __restrict__ oBh, bf16* __restrict__ oBl,
             int NJ, int NTC, int KTC, int CHUNKS, int KCA, int N,
             const float* __restrict__ add, const unsigned char* __restrict__ mask) {
    constexpr int CPW = NT / 4;            // cols per warp
    constexpr int PJ  = CPW / 16;          // B ldsm.x4 per term (1 or 2)
    constexpr int JT  = CPW / 8;           // j tiles per warp (2 or 4)
    constexpr int BS  = NT * 64;           // B bytes per term per chunk
    constexpr int STG = 2 * 8192 + 2 * BS;

    extern __shared__ char sm[];
    const uint32_t smb = smem_u32(sm);
    const uint32_t fullb = smb, emptyb = smb + 48;
    const uint32_t stg0 = smb + 128;

    const int tid = threadIdx.x;
    const int wid = tid >> 5, lane = tid & 31;
    const int wm = wid & 1, wn = wid >> 1;
    const int g = lane >> 2, t4 = lane & 3;

    if (tid == 0) {
#pragma unroll
        for (int s = 0; s < NST; s++) {
            MBAR_INIT(fullb + s * 16, 1);
            MBAR_INIT(emptyb + s * 16, 8);
        }
        FENCE_ASYNC();
    }
    __syncthreads();

    const int G = gridDim.x;
    const int bid = blockIdx.x;
    const int njm = (bid < NJ) ? ((NJ - bid + G - 1) / G) : 0;
    const int T = njm * CHUNKS;

    auto issue = [&](int t) {
        int jl = t / CHUNKS, c = t - jl * CHUNKS;
        int job = bid + jl * G;
        int n = job % NTC;
        int r = job / NTC;
        int kt = (KTC == 2) ? (r & 1) : 0;
        int m = (KTC == 2) ? (r >> 1) : r;
        int cg = kt * CHUNKS + c;
        int s = t % NST;
        uint32_t dst = stg0 + s * STG;
        uint32_t mb = fullb + s * 16;
        MBAR_EXPECT_TX(mb, STG);
        const char* a0 = (const char*)Ah + (((size_t)m * KCA + cg) << 13);
        const char* a1 = (const char*)Al + (((size_t)m * KCA + cg) << 13);
        int bn = n * NT;
        int pB = bn >> 7;
        uint32_t ho = (uint32_t)(bn & 64) << 6;
        const char* b0 = (const char*)Bh + (((size_t)pB * KCA + cg) << 13) + ho;
        const char* b1 = (const char*)Bl + (((size_t)pB * KCA + cg) << 13) + ho;
        BULK_G2S(dst,             a0, 8192, mb);
        BULK_G2S(dst + 8192,      a1, 8192, mb);
        BULK_G2S(dst + 16384,     b0, BS,   mb);
        BULK_G2S(dst + 16384 + BS, b1, BS,  mb);
    };

    if (tid == 0) {
        int pre = T < NST ? T : NST;
        for (int t = 0; t < pre; t++) issue(t);
    }

    float acc[4][JT][4];
#pragma unroll
    for (int i = 0; i < 4; i++)
#pragma unroll
        for (int j = 0; j < JT; j++)
#pragma unroll
            for (int r = 0; r < 4; r++) acc[i][j][r] = 0.f;

    const uint32_t rA = (uint32_t)(lane & 15);
    const uint32_t qA = (uint32_t)(lane >> 4) * 16;
    const uint32_t rB = (uint32_t)(((lane >> 4) & 1) * 8 + (lane & 7));
    const uint32_t qB = (uint32_t)((lane >> 3) & 1) * 16;

    int bm = 0, bn = 0;

    for (int t = 0; t < T; t++) {
        int jl = t / CHUNKS, c = t - jl * CHUNKS;
        if (c == 0) {
            int job = bid + jl * G;
            int n = job % NTC;
            int r = job / NTC;
            int m = (KTC == 2) ? (r >> 1) : r;
            bm = m * 128;
            bn = n * NT;
        }
        const int s = t % NST;
        const int u = t / NST;
        MBAR_WAIT(fullb + s * 16, u & 1);

        const uint32_t st = stg0 + s * STG;
#pragma unroll
        for (int ks = 0; ks < 2; ks++) {
            uint32_t Ahf[4][4], Alf[4][4], Bhf[PJ][4], Blf[PJ][4];
#pragma unroll
            for (int i = 0; i < 4; i++) {
                uint32_t o = (wm * 64 + i * 16 + rA) * 64 + qA + ks * 32;
                o = SWZ(o);
                ldsm4(Ahf[i], st + o);
                ldsm4(Alf[i], st + 8192 + o);
            }
#pragma unroll
            for (int p = 0; p < PJ; p++) {
                uint32_t o = (wn * CPW + p * 16 + rB) * 64 + qB + ks * 32;
                o = SWZ(o);
                ldsm4(Bhf[p], st + 16384 + o);
                ldsm4(Blf[p], st + 16384 + BS + o);
            }
#pragma unroll
            for (int i = 0; i < 4; i++)
#pragma unroll
                for (int j = 0; j < JT; j++) {
                    const uint32_t* bh = &Bhf[j >> 1][(j & 1) * 2];
                    const uint32_t* bl = &Blf[j >> 1][(j & 1) * 2];
                    mma16816(acc[i][j], Ahf[i], bh);
                    mma16816(acc[i][j], Alf[i], bh);
                    mma16816(acc[i][j], Ahf[i], bl);
                }
        }
        __syncwarp();
        if (lane == 0) MBAR_ARRIVE(emptyb + s * 16);
        if (tid == 0 && t + NST < T) {
            MBAR_WAIT(emptyb + s * 16, u & 1);
            issue(t + NST);
        }

        if (c == CHUNKS - 1) {
            // epilogue for this job
#pragma unroll
            for (int i = 0; i < 4; i++) {
                int row0 = bm + wm * 64 + i * 16 + g;
#pragma unroll
                for (int j = 0; j < JT; j++) {
                    int col = bn + wn * CPW + j * 8 + 2 * t4;
                    float b0 = (EPI == E_ATOMIC) ? 0.f : bias[col];
                    float b1 = (EPI == E_ATOMIC) ? 0.f : bias[col + 1];
#pragma unroll
                    for (int half = 0; half < 2; half++) {
                        int row = row0 + half * 8;
                        float v0 = acc[i][j][half * 2 + 0] + b0;
                        float v1 = acc[i][j][half * 2 + 1] + b1;
                        if (EPI == E_MASK_BF16) {
                            if (mask[row]) { v0 = 0.f; v1 = 0.f; }
                            __nv_bfloat162 pk;
                            pk.x = __float2bfloat16(v0); pk.y = __float2bfloat16(v1);
                            *(uint32_t*)(oBh + (size_t)row * N + col) = *(uint32_t*)&pk;
                        } else if (EPI == E_OFFATTN) {
                            if (bn == 256)
                                *(float2*)(outF2 + (size_t)row * 128 + (col - 256)) = make_float2(v0, v1);
                            else
                                *(float2*)(outF + (size_t)row * 256 + col) = make_float2(v0, v1);
                        } else if (EPI == E_ADD) {
                            float2 r2 = *(const float2*)(add + (size_t)row * N + col);
                            *(float2*)(outF + (size_t)row * N + col) = make_float2(v0 + r2.x, v1 + r2.y);
                        } else if (EPI == E_RELU_SPLIT) {
                            v0 = fmaxf(v0, 0.f); v1 = fmaxf(v1, 0.f);
                            uint32_t hi, lo;
                            split2(v0, v1, hi, lo);
                            size_t off = blk_off(row, col, N);
                            *(uint32_t*)((char*)oBh + off) = hi;
                            *(uint32_t*)((char*)oBl + off) = lo;
                        } else if (EPI == E_ATOMIC) {
                            atomicAdd(outF + (size_t)row * N + col, v0);
                            atomicAdd(outF + (size_t)row * N + col + 1, v1);
                        }
                    }
                }
            }
#pragma unroll
            for (int i = 0; i < 4; i++)
#pragma unroll
                for (int j = 0; j < JT; j++)
#pragma unroll
                    for (int r = 0; r < 4; r++) acc[i][j][r] = 0.f;
        }
    }
}

// ---------------- msdeform sampling v2 ----------------
// 2 tokens per block (256 thr). Warp = 2 heads. Phase 1: each lane computes one
// sampling point (softmax weight + 4 taps) -> smem. Phase 2: lanes gather bf16x2
// channel pairs and accumulate.
__global__ void sample_kernel(const float* __restrict__ ref,
                              bf16* __restrict__ ah, bf16* __restrict__ al) {
    __shared__ int   s_off[8][32][4];
    __shared__ float s_w  [8][32][4];

    const int wid = threadIdx.x >> 5, lane = threadIdx.x & 31;
    const int tw = wid & 3;
    const int m = blockIdx.x * 2 + (wid >> 2);
    const int b = m / NTOK;
    const int hh = lane >> 4;
    const int head = (tw << 1) | hh;
    const int pt = lane & 15;

    // ---- phase 1: per-point computation ----
    float logit = g_attn[(size_t)m * 128 + head * 16 + pt];
    float mx = logit;
#pragma unroll
    for (int o = 8; o; o >>= 1) mx = fmaxf(mx, __shfl_xor_sync(0xffffffffu, mx, o, 16));
    float e = __expf(logit - mx);
    float sum = e;
#pragma unroll
    for (int o = 8; o; o >>= 1) sum += __shfl_xor_sync(0xffffffffu, sum, o, 16);
    float aw = e / sum;

    const int l = pt >> 2;
    const int Wl = c_lvl_W[l];
    float2 oxy = ((const float2*)g_off)[(size_t)m * 128 + head * 16 + pt];
    float2 rxy = ((const float2*)ref)[(size_t)m * 4 + l];
    float x = fmaf(rxy.x, (float)Wl, oxy.x) - 0.5f;
    float y = fmaf(rxy.y, (float)Wl, oxy.y) - 0.5f;
    float x0f = floorf(x), y0f = floorf(y);
    float fx = x - x0f, fy = y - y0f;
    int x0 = (int)x0f, y0 = (int)y0f;
    int x1 = x0 + 1, y1 = y0 + 1;
    bool vx0 = (x0 >= 0) & (x0 < Wl);
    bool vx1 = (x1 >= 0) & (x1 < Wl);
    bool vy0 = (y0 >= 0) & (y0 < Wl);
    bool vy1 = (y1 >= 0) & (y1 < Wl);
    int xc0 = min(max(x0, 0), Wl - 1), xc1 = min(max(x1, 0), Wl - 1);
    int yc0 = min(max(y0, 0), Wl - 1), yc1 = min(max(y1, 0), Wl - 1);
    float w00 = (vx0 & vy0) ? aw * (1.f - fx) * (1.f - fy) : 0.f;
    float w10 = (vx1 & vy0) ? aw * fx * (1.f - fy) : 0.f;
    float w01 = (vx0 & vy1) ? aw * (1.f - fx) * fy : 0.f;
    float w11 = (vx1 & vy1) ? aw * fx * fy : 0.f;
    int rowbase = b * NTOK + c_lvl_start[l];
    // byte offsets into g_valbf (row stride 256 bf16 = 512B; head offset 32 ch = 64B)
    int hb = head * 64;
    s_off[wid][lane][0] = (rowbase + yc0 * Wl + xc0) * 512 + hb;
    s_off[wid][lane][1] = (rowbase + yc0 * Wl + xc1) * 512 + hb;
    s_off[wid][lane][2] = (rowbase + yc1 * Wl + xc0) * 512 + hb;
    s_off[wid][lane][3] = (rowbase + yc1 * Wl + xc1) * 512 + hb;
    s_w[wid][lane][0] = w00; s_w[wid][lane][1] = w10;
    s_w[wid][lane][2] = w01; s_w[wid][lane][3] = w11;
    __syncwarp();

    // ---- phase 2: gather ----
    const int c2 = lane & 15;     // channel pair 0..15 for my head (hh)
    float accx = 0.f, accy = 0.f;
    const char* vb = (const char*)g_valbf + c2 * 4;
#pragma unroll
    for (int s = 0; s < 16; s++) {
        int slot = (hh << 4) | s;
        int4 io = *(const int4*)s_off[wid][slot];
        float4 wv = *(const float4*)s_w[wid][slot];
        __nv_bfloat162 v;
        float2 vf;
        v = *(const __nv_bfloat162*)(vb + io.x); vf = __bfloat1622float2(v);
        accx = fmaf(wv.x, vf.x, accx); accy = fmaf(wv.x, vf.y, accy);
        v = *(const __nv_bfloat162*)(vb + io.y); vf = __bfloat1622float2(v);
        accx = fmaf(wv.y, vf.x, accx); accy = fmaf(wv.y, vf.y, accy);
        v = *(const __nv_bfloat162*)(vb + io.z); vf = __bfloat1622float2(v);
        accx = fmaf(wv.z, vf.x, accx); accy = fmaf(wv.z, vf.y, accy);
        v = *(const __nv_bfloat162*)(vb + io.w); vf = __bfloat1622float2(v);
        accx = fmaf(wv.w, vf.x, accx); accy = fmaf(wv.w, vf.y, accy);
    }

    // write split bf16 pair (blocked layout)
    uint32_t hi, lo;
    split2(accx, accy, hi, lo);
    int k0 = head * 32 + c2 * 2;
    size_t off = blk_off(m, k0, 256);
    *(uint32_t*)((char*)ah + off) = hi;
    *(uint32_t*)((char*)al + off) = lo;
}

// ---------------- LayerNorm over D=256 ----------------
// MODE 0: plain (write out). MODE 1: LN1 (write out fp32 + blocked split + t2init = o + b2)
template <int MODE>
__global__ void ln_kernel(const float* __restrict__ in, const float* __restrict__ g,
                          const float* __restrict__ be, float* __restrict__ out,
                          bf16* __restrict__ oh, bf16* __restrict__ ol,
                          float* __restrict__ t2i, const float* __restrict__ b2) {
    int m = blockIdx.x;
    int t = threadIdx.x;
    float v = in[(size_t)m * Dd + t];
    float s = v, sq = v * v;
#pragma unroll
    for (int o = 16; o; o >>= 1) {
        s += __shfl_xor_sync(0xffffffffu, s, o);
        sq += __shfl_xor_sync(0xffffffffu, sq, o);
    }
    __shared__ float ss[8], ssq[8];
    __shared__ float s_mean, s_rstd;
    if ((t & 31) == 0) { ss[t >> 5] = s; ssq[t >> 5] = sq; }
    __syncthreads();
    if (t == 0) {
        float ts = 0.f, tsq = 0.f;
#pragma unroll
        for (int i = 0; i < 8; i++) { ts += ss[i]; tsq += ssq[i]; }
        float mean = ts * (1.f / Dd);
        float var = tsq * (1.f / Dd) - mean * mean;
        s_mean = mean;
        s_rstd = rsqrtf(var + 1e-5f);
    }
    __syncthreads();
    float o = (v - s_mean) * s_rstd * g[t] + be[t];
    out[(size_t)m * Dd + t] = o;
    if (MODE == 1) {
        bf16 hb, lb;
        splitf(o, hb, lb);
        size_t off = blk_off(m, t, 256);
        *(bf16*)((char*)oh + off) = hb;
        *(bf16*)((char*)ol + off) = lb;
        t2i[(size_t)m * Dd + t] = o + b2[t];
    }
}

// ---------------- launch ----------------
extern "C" void kernel_launch(void* const* d_in, const int* in_sizes, int n_in,
                              void* d_out, int out_size) {
    const float* src   = (const float*)d_in[0];
    const float* pos   = (const float*)d_in[1];
    const float* ref   = (const float*)d_in[2];
    const float* w_val = (const float*)d_in[3];
    const float* b_val = (const float*)d_in[4];
    const float* w_off = (const float*)d_in[5];
    const float* b_off = (const float*)d_in[6];
    const float* w_att = (const float*)d_in[7];
    const float* b_att = (const float*)d_in[8];
    const float* w_out = (const float*)d_in[9];
    const float* b_out = (const float*)d_in[10];
    const float* g1    = (const float*)d_in[11];
    const float* be1   = (const float*)d_in[12];
    const float* w1    = (const float*)d_in[13];
    const float* b1    = (const float*)d_in[14];
    const float* w2    = (const float*)d_in[15];
    const float* b2    = (const float*)d_in[16];
    const float* g2    = (const float*)d_in[17];
    const float* be2   = (const float*)d_in[18];
    const unsigned char* mask = (const unsigned char*)d_in[21];

    bf16 *srch, *srcl, *qh, *ql, *ah, *al, *xh, *xl, *hh, *hl, *valbf;
    bf16 *wvh, *wvl, *wch, *wcl, *woh, *wol, *w1h, *w1l, *w2h, *w2l;
    float *p_off, *p_attn, *p_t1, *p_x, *p_t2, *p_bcomb;
    cudaGetSymbolAddress((void**)&srch, g_srch);  cudaGetSymbolAddress((void**)&srcl, g_srcl);
    cudaGetSymbolAddress((void**)&qh, g_qh);      cudaGetSymbolAddress((void**)&ql, g_ql);
    cudaGetSymbolAddress((void**)&ah, g_ah);      cudaGetSymbolAddress((void**)&al, g_al);
    cudaGetSymbolAddress((void**)&xh, g_xh);      cudaGetSymbolAddress((void**)&xl, g_xl);
    cudaGetSymbolAddress((void**)&hh, g_hh);      cudaGetSymbolAddress((void**)&hl, g_hl);
    cudaGetSymbolAddress((void**)&valbf, g_valbf);
    cudaGetSymbolAddress((void**)&wvh, g_wvh);    cudaGetSymbolAddress((void**)&wvl, g_wvl);
    cudaGetSymbolAddress((void**)&wch, g_wch);    cudaGetSymbolAddress((void**)&wcl, g_wcl);
    cudaGetSymbolAddress((void**)&woh, g_woh);    cudaGetSymbolAddress((void**)&wol, g_wol);
    cudaGetSymbolAddress((void**)&w1h, g_w1h);    cudaGetSymbolAddress((void**)&w1l, g_w1l);
    cudaGetSymbolAddress((void**)&w2h, g_w2h);    cudaGetSymbolAddress((void**)&w2l, g_w2l);
    cudaGetSymbolAddress((void**)&p_off, g_off);
    cudaGetSymbolAddress((void**)&p_attn, g_attn);
    cudaGetSymbolAddress((void**)&p_t1, g_t1);
    cudaGetSymbolAddress((void**)&p_x, g_x);
    cudaGetSymbolAddress((void**)&p_t2, g_t2);
    cudaGetSymbolAddress((void**)&p_bcomb, g_bcomb);

    const int M = Mrows;
    const int SM64  = 128 + NST * (2 * 8192 + 2 * 64 * 64);    // 73856
    const int SM128 = 128 + NST * (2 * 8192 + 2 * 128 * 64);   // 98432
    cudaFuncSetAttribute(tc_gemm<64,  E_MASK_BF16>, cudaFuncAttributeMaxDynamicSharedMemorySize, SM64);
    cudaFuncSetAttribute(tc_gemm<128, E_OFFATTN>,   cudaFuncAttributeMaxDynamicSharedMemorySize, SM128);
    cudaFuncSetAttribute(tc_gemm<64,  E_ADD>,       cudaFuncAttributeMaxDynamicSharedMemorySize, SM64);
    cudaFuncSetAttribute(tc_gemm<128, E_RELU_SPLIT>,cudaFuncAttributeMaxDynamicSharedMemorySize, SM128);
    cudaFuncSetAttribute(tc_gemm<64,  E_ATOMIC>,    cudaFuncAttributeMaxDynamicSharedMemorySize, SM64);

    // prep
    src_q_split<<<(M * Dd / 4) / 256, 256>>>(src, pos, srch, srcl, qh, ql);
    WSplitArgs wa;
    wa.s[0] = w_val; wa.h[0] = wvh; wa.l[0] = wvl; wa.n4[0] = Dd * Dd / 4;  wa.kshift[0] = 8;  wa.rowoff[0] = 0;
    wa.s[1] = w_off; wa.h[1] = wch; wa.l[1] = wcl; wa.n4[1] = Dd * Dd / 4;  wa.kshift[1] = 8;  wa.rowoff[1] = 0;
    wa.s[2] = w_att; wa.h[2] = wch; wa.l[2] = wcl; wa.n4[2] = 128 * Dd / 4; wa.kshift[2] = 8;  wa.rowoff[2] = 256;
    wa.s[3] = w_out; wa.h[3] = woh; wa.l[3] = wol; wa.n4[3] = Dd * Dd / 4;  wa.kshift[3] = 8;  wa.rowoff[3] = 0;
    wa.s[4] = w1;    wa.h[4] = w1h; wa.l[4] = w1l; wa.n4[4] = FFd * Dd / 4; wa.kshift[4] = 8;  wa.rowoff[4] = 0;
    wa.s[5] = w2;    wa.h[5] = w2h; wa.l[5] = w2l; wa.n4[5] = Dd * FFd / 4; wa.kshift[5] = 10; wa.rowoff[5] = 0;
    wsplit_all<<<dim3(256, 6), 256>>>(wa);
    pack_bias<<<1, 384>>>(b_off, b_att, p_bcomb);

    // value = mask(src @ Wv^T + b) -> bf16 row-major.  jobs: 170m x 4n
    tc_gemm<64, E_MASK_BF16><<<GPERS, 256, SM64>>>(
        srch, srcl, wvh, wvl, b_val, nullptr, nullptr, valbf, nullptr,
        680, 4, 1, 8, 8, Dd, nullptr, mask);
    // [off ; attn] = q @ Wc^T + b.  jobs: 170m x 3n
    tc_gemm<128, E_OFFATTN><<<GPERS, 256, SM128>>>(
        qh, ql, wch, wcl, p_bcomb, p_off, p_attn, nullptr, nullptr,
        510, 3, 1, 8, 8, 384, nullptr, nullptr);
    // msdeform -> blocked split a
    sample_kernel<<<M / 2, 256>>>(ref, ah, al);
    // t1 = src + a @ Wo^T + b.  jobs: 170m x 4n
    tc_gemm<64, E_ADD><<<GPERS, 256, SM64>>>(
        ah, al, woh, wol, b_out, p_t1, nullptr, nullptr, nullptr,
        680, 4, 1, 8, 8, Dd, src, nullptr);
    // x = LN(t1); also t2init = x + b2
    ln_kernel<1><<<M, 256>>>(p_t1, g1, be1, p_x, xh, xl, p_t2, b2);
    // h = relu(x @ W1^T + b1).  jobs: 170m x 8n
    tc_gemm<128, E_RELU_SPLIT><<<GPERS, 256, SM128>>>(
        xh, xl, w1h, w1l, b1, nullptr, nullptr, hh, hl,
        1360, 8, 1, 8, 8, FFd, nullptr, nullptr);
    // t2 += h @ W2^T (K-split x2, atomic).  jobs: 170m x 4n x 2k
    tc_gemm<64, E_ATOMIC><<<GPERS, 256, SM64>>>(
        hh, hl, w2h, w2l, nullptr, p_t2, nullptr, nullptr, nullptr,
        1360, 4, 2, 16, 32, Dd, nullptr, nullptr);
    // out = LN(t2)
    ln_kernel<0><<<M, 256>>>(p_t2, g2, be2, (float*)d_out, nullptr, nullptr, nullptr, nullptr);
}

// round 8
// speedup vs baseline: 3.6033x; 1.2570x over previous
#include <cuda_runtime.h>
#include <cuda_fp16.h>
#include <math.h>
#include <stdint.h>

typedef __half hf;

// ---------------- problem constants ----------------
#define Bb 4
#define NTOK 5440
#define Mrows (Bb * NTOK)   // 21760
#define Dd 256
#define FFd 1024
#define NHh 8
#define NLl 4
#define NPp 4
#define DHh 32
#define GPERS 304

__device__ __constant__ int c_lvl_W[4]     = {64, 32, 16, 8};
__device__ __constant__ int c_lvl_start[4] = {0, 4096, 5120, 5376};

// ---------------- scratch (device globals) ----------------
__device__ hf    g_srch[Mrows * Dd], g_srcl[Mrows * Dd];
__device__ hf    g_qh  [Mrows * Dd], g_ql  [Mrows * Dd];
__device__ hf    g_ah  [Mrows * Dd], g_al  [Mrows * Dd];
__device__ hf    g_xh  [Mrows * Dd], g_xl  [Mrows * Dd];
__device__ hf    g_hh  [Mrows * FFd], g_hl [Mrows * FFd];
__device__ hf    g_valhf[Mrows * Dd];          // value fp16 row-major (sampler)
__device__ float g_off  [Mrows * Dd];
__device__ float g_attn [Mrows * 128];
__device__ float g_t1   [Mrows * Dd];
__device__ float g_x    [Mrows * Dd];
__device__ float g_t2   [Mrows * Dd];
// fp16 weights (single precision term), blocked layout
__device__ hf g_wv[Dd*Dd];
__device__ hf g_wc[384*Dd];
__device__ hf g_wo[Dd*Dd];
__device__ hf g_w1[FFd*Dd];
__device__ hf g_w2[Dd*FFd];
__device__ float g_bcomb[384];

// ---------------- blocked layout ----------------
__device__ __forceinline__ size_t blk_off(int row, int k, int K) {
    uint32_t o = (uint32_t)(row & 127) * 64 + (uint32_t)(k & 31) * 2;
    o = o ^ ((o >> 3) & 0x70);
    return ((size_t)((row >> 7) * (K >> 5) + (k >> 5)) << 13) + o;
}
#define SWZ(o) ((o) ^ (((o) >> 3) & 0x70))

// ---------------- PTX helpers ----------------
__device__ __forceinline__ uint32_t smem_u32(const void* p) {
    uint32_t a;
    asm("{ .reg .u64 t; cvta.to.shared.u64 t, %1; cvt.u32.u64 %0, t; }" : "=r"(a) : "l"(p));
    return a;
}
#define MBAR_INIT(addr, cnt) \
    asm volatile("mbarrier.init.shared.b64 [%0], %1;" :: "r"((uint32_t)(addr)), "r"((uint32_t)(cnt)) : "memory")
#define MBAR_ARRIVE(addr) \
    asm volatile("mbarrier.arrive.shared.b64 _, [%0];" :: "r"((uint32_t)(addr)) : "memory")
#define MBAR_EXPECT_TX(addr, tx) \
    asm volatile("mbarrier.arrive.expect_tx.shared.b64 _, [%0], %1;" :: "r"((uint32_t)(addr)), "r"((uint32_t)(tx)) : "memory")
#define BULK_G2S(dst, src, bytes, mbar) \
    asm volatile("cp.async.bulk.shared::cluster.global.mbarrier::complete_tx::bytes [%0], [%1], %2, [%3];" \
        :: "r"((uint32_t)(dst)), "l"(src), "r"((uint32_t)(bytes)), "r"((uint32_t)(mbar)) : "memory")
#define FENCE_ASYNC() asm volatile("fence.proxy.async.shared::cta;" ::: "memory")

#define MBAR_WAIT(addr, par) do { \
    uint32_t _m = (uint32_t)(addr); uint32_t _p = (uint32_t)(par); uint32_t _d; \
    asm volatile("{\n\t.reg .pred p;\n\t" \
        "mbarrier.try_wait.parity.acquire.cta.shared::cta.b64 p, [%1], %2;\n\t" \
        "selp.b32 %0, 1, 0, p;\n\t}" : "=r"(_d) : "r"(_m), "r"(_p) : "memory"); \
    if (!_d) { \
        asm volatile("{\n\t.reg .pred P1;\n\t" \
            "WL_%=:\n\t" \
            "mbarrier.try_wait.parity.acquire.cta.shared::cta.b64 P1, [%0], %1, 0x989680;\n\t" \
            "@P1 bra.uni WD_%=;\n\t" \
            "bra.uni WL_%=;\n\t" \
            "WD_%=:\n\t}" :: "r"(_m), "r"(_p) : "memory"); \
    } } while (0)

__device__ __forceinline__ void ldsm4(uint32_t* r, uint32_t a) {
    asm volatile("ldmatrix.sync.aligned.m8n8.x4.shared.b16 {%0,%1,%2,%3}, [%4];"
        : "=r"(r[0]), "=r"(r[1]), "=r"(r[2]), "=r"(r[3]) : "r"(a));
}
__device__ __forceinline__ void mma16816(float* d, const uint32_t* a, const uint32_t* b) {
    asm volatile("mma.sync.aligned.m16n8k16.row.col.f32.f16.f16.f32 "
        "{%0,%1,%2,%3}, {%4,%5,%6,%7}, {%8,%9}, {%0,%1,%2,%3};"
        : "+f"(d[0]), "+f"(d[1]), "+f"(d[2]), "+f"(d[3])
        : "r"(a[0]), "r"(a[1]), "r"(a[2]), "r"(a[3]), "r"(b[0]), "r"(b[1]));
}

// ---------------- fp16 split helpers ----------------
__device__ __forceinline__ void splitf(float v, hf& h, hf& l) {
    h = __float2half_rn(v);
    l = __float2half_rn(v - __half2float(h));
}
__device__ __forceinline__ void split4(float4 v, uint2& hi, uint2& lo) {
    hf h0, l0, h1, l1, h2, l2, h3, l3;
    splitf(v.x, h0, l0); splitf(v.y, h1, l1);
    splitf(v.z, h2, l2); splitf(v.w, h3, l3);
    __half2 a = __halves2half2(h0, h1), b = __halves2half2(h2, h3);
    hi.x = *(uint32_t*)&a; hi.y = *(uint32_t*)&b;
    a = __halves2half2(l0, l1); b = __halves2half2(l2, l3);
    lo.x = *(uint32_t*)&a; lo.y = *(uint32_t*)&b;
}
__device__ __forceinline__ void split2(float x, float y, uint32_t& hi, uint32_t& lo) {
    hf hx, lx, hy, ly;
    splitf(x, hx, lx); splitf(y, hy, ly);
    __half2 a = __halves2half2(hx, hy); hi = *(uint32_t*)&a;
    a = __halves2half2(lx, ly);         lo = *(uint32_t*)&a;
}
__device__ __forceinline__ uint2 conv4(float4 v) {
    __half2 a = __floats2half2_rn(v.x, v.y);
    __half2 b = __floats2half2_rn(v.z, v.w);
    uint2 r; r.x = *(uint32_t*)&a; r.y = *(uint32_t*)&b;
    return r;
}

// ---------------- prep kernels ----------------
__global__ void src_q_split(const float* __restrict__ src, const float* __restrict__ pos,
                            hf* __restrict__ sh, hf* __restrict__ sl,
                            hf* __restrict__ qh, hf* __restrict__ ql) {
    int i = blockIdx.x * blockDim.x + threadIdx.x;
    int e = i * 4;
    int m = e >> 8, k = e & 255;
    size_t off = blk_off(m, k, 256);
    float4 s = ((const float4*)src)[i];
    float4 p = ((const float4*)pos)[i];
    uint2 hi, lo;
    split4(s, hi, lo);
    *(uint2*)((char*)sh + off) = hi;
    *(uint2*)((char*)sl + off) = lo;
    float4 q = make_float4(s.x + p.x, s.y + p.y, s.z + p.z, s.w + p.w);
    split4(q, hi, lo);
    *(uint2*)((char*)qh + off) = hi;
    *(uint2*)((char*)ql + off) = lo;
}

struct WConvArgs {
    const float* s[5];
    hf* h[5];
    int n4[5];
    int kshift[5];
    int rowoff[5];
};
__global__ void wconv_all(WConvArgs a) {
    int seg = blockIdx.y;
    int i = blockIdx.x * blockDim.x + threadIdx.x;
    if (i >= a.n4[seg]) return;
    int ks = a.kshift[seg];
    int K = 1 << ks;
    int e = i * 4;
    int m = (e >> ks) + a.rowoff[seg];
    int k = e & (K - 1);
    size_t off = blk_off(m, k, K);
    *(uint2*)((char*)a.h[seg] + off) = conv4(((const float4*)a.s[seg])[i]);
}

__global__ void pack_bias(const float* __restrict__ bo, const float* __restrict__ ba,
                          float* __restrict__ dst) {
    int i = threadIdx.x;
    dst[i] = (i < 256) ? bo[i] : ba[i - 256];
}

// ---------------- persistent bulk-copy HMMA GEMM (fp16 2-term) ----------------
// C = (Ah+Al) @ B^T.  M-tile 128, N-tile NT, chunk 32, flat job list, 3-stage bulk pipeline.
#define NST 3
enum { E_MASK_F16 = 0, E_OFFATTN = 1, E_ADD = 2, E_RELU_SPLIT = 3, E_ATOMIC = 4 };

template <int NT, int EPI>
__global__ __launch_bounds__(256, 2)
void tc_gemm(const hf* __restrict__ Ah, const hf* __restrict__ Al,
             const hf* __restrict__ B,
             const float* __restrict__ bias,
             float* __restrict__ outF, float* __restrict__ outF2,
             hf* __restrict__ oFh, hf* __restrict__ oFl,
             int NJ, int NTC, int KTC, int CHUNKS, int KCA, int N,
             const float* __restrict__ add, const unsigned char* __restrict__ mask) {
    constexpr int CPW = NT / 4;
    constexpr int PJ  = CPW / 16;
    constexpr int JT  = CPW / 8;
    constexpr int BS  = NT * 64;
    constexpr int STG = 2 * 8192 + BS;

    extern __shared__ char sm[];
    const uint32_t smb = smem_u32(sm);
    const uint32_t fullb = smb, emptyb = smb + 48;
    const uint32_t stg0 = smb + 128;

    const int tid = threadIdx.x;
    const int wid = tid >> 5, lane = tid & 31;
    const int wm = wid & 1, wn = wid >> 1;
    const int g = lane >> 2, t4 = lane & 3;

    if (tid == 0) {
#pragma unroll
        for (int s = 0; s < NST; s++) {
            MBAR_INIT(fullb + s * 16, 1);
            MBAR_INIT(emptyb + s * 16, 8);
        }
        FENCE_ASYNC();
    }
    __syncthreads();

    const int G = gridDim.x;
    const int bid = blockIdx.x;
    const int njm = (bid < NJ) ? ((NJ - bid + G - 1) / G) : 0;
    const int T = njm * CHUNKS;

    auto issue = [&](int t) {
        int jl = t / CHUNKS, c = t - jl * CHUNKS;
        int job = bid + jl * G;
        int n = job % NTC;
        int r = job / NTC;
        int kt = (KTC == 2) ? (r & 1) : 0;
        int m = (KTC == 2) ? (r >> 1) : r;
        int cg = kt * CHUNKS + c;
        int s = t % NST;
        uint32_t dst = stg0 + s * STG;
        uint32_t mb = fullb + s * 16;
        MBAR_EXPECT_TX(mb, STG);
        const char* a0 = (const char*)Ah + (((size_t)m * KCA + cg) << 13);
        const char* a1 = (const char*)Al + (((size_t)m * KCA + cg) << 13);
        int bn = n * NT;
        int pB = bn >> 7;
        uint32_t ho = (uint32_t)(bn & 64) << 6;
        const char* b0 = (const char*)B + (((size_t)pB * KCA + cg) << 13) + ho;
        BULK_G2S(dst,         a0, 8192, mb);
        BULK_G2S(dst + 8192,  a1, 8192, mb);
        BULK_G2S(dst + 16384, b0, BS,   mb);
    };

    if (tid == 0) {
        int pre = T < NST ? T : NST;
        for (int t = 0; t < pre; t++) issue(t);
    }

    float acc[4][JT][4];
#pragma unroll
    for (int i = 0; i < 4; i++)
#pragma unroll
        for (int j = 0; j < JT; j++)
#pragma unroll
            for (int r = 0; r < 4; r++) acc[i][j][r] = 0.f;

    const uint32_t rA = (uint32_t)(lane & 15);
    const uint32_t qA = (uint32_t)(lane >> 4) * 16;
    const uint32_t rB = (uint32_t)(((lane >> 4) & 1) * 8 + (lane & 7));
    const uint32_t qB = (uint32_t)((lane >> 3) & 1) * 16;

    int bm = 0, bn = 0;

    for (int t = 0; t < T; t++) {
        int jl = t / CHUNKS, c = t - jl * CHUNKS;
        if (c == 0) {
            int job = bid + jl * G;
            int n = job % NTC;
            int r = job / NTC;
            int m = (KTC == 2) ? (r >> 1) : r;
            bm = m * 128;
            bn = n * NT;
        }
        const int s = t % NST;
        const int u = t / NST;
        MBAR_WAIT(fullb + s * 16, u & 1);

        const uint32_t st = stg0 + s * STG;
#pragma unroll
        for (int ks = 0; ks < 2; ks++) {
            uint32_t Ahf[4][4], Alf[4][4], Bf[PJ][4];
#pragma unroll
            for (int i = 0; i < 4; i++) {
                uint32_t o = (wm * 64 + i * 16 + rA) * 64 + qA + ks * 32;
                o = SWZ(o);
                ldsm4(Ahf[i], st + o);
                ldsm4(Alf[i], st + 8192 + o);
            }
#pragma unroll
            for (int p = 0; p < PJ; p++) {
                uint32_t o = (wn * CPW + p * 16 + rB) * 64 + qB + ks * 32;
                o = SWZ(o);
                ldsm4(Bf[p], st + 16384 + o);
            }
#pragma unroll
            for (int i = 0; i < 4; i++)
#pragma unroll
                for (int j = 0; j < JT; j++) {
                    const uint32_t* bp = &Bf[j >> 1][(j & 1) * 2];
                    mma16816(acc[i][j], Ahf[i], bp);
                    mma16816(acc[i][j], Alf[i], bp);
                }
        }
        __syncwarp();
        if (lane == 0) MBAR_ARRIVE(emptyb + s * 16);
        if (tid == 0 && t + NST < T) {
            MBAR_WAIT(emptyb + s * 16, u & 1);
            issue(t + NST);
        }

        if (c == CHUNKS - 1) {
#pragma unroll
            for (int i = 0; i < 4; i++) {
                int row0 = bm + wm * 64 + i * 16 + g;
#pragma unroll
                for (int j = 0; j < JT; j++) {
                    int col = bn + wn * CPW + j * 8 + 2 * t4;
                    float b0 = (EPI == E_ATOMIC) ? 0.f : bias[col];
                    float b1 = (EPI == E_ATOMIC) ? 0.f : bias[col + 1];
#pragma unroll
                    for (int half = 0; half < 2; half++) {
                        int row = row0 + half * 8;
                        float v0 = acc[i][j][half * 2 + 0] + b0;
                        float v1 = acc[i][j][half * 2 + 1] + b1;
                        if (EPI == E_MASK_F16) {
                            if (mask[row]) { v0 = 0.f; v1 = 0.f; }
                            __half2 pk = __floats2half2_rn(v0, v1);
                            *(uint32_t*)(oFh + (size_t)row * N + col) = *(uint32_t*)&pk;
                        } else if (EPI == E_OFFATTN) {
                            if (bn == 256)
                                *(float2*)(outF2 + (size_t)row * 128 + (col - 256)) = make_float2(v0, v1);
                            else
                                *(float2*)(outF + (size_t)row * 256 + col) = make_float2(v0, v1);
                        } else if (EPI == E_ADD) {
                            float2 r2 = *(const float2*)(add + (size_t)row * N + col);
                            *(float2*)(outF + (size_t)row * N + col) = make_float2(v0 + r2.x, v1 + r2.y);
                        } else if (EPI == E_RELU_SPLIT) {
                            v0 = fmaxf(v0, 0.f); v1 = fmaxf(v1, 0.f);
                            uint32_t hi, lo;
                            split2(v0, v1, hi, lo);
                            size_t off = blk_off(row, col, N);
                            *(uint32_t*)((char*)oFh + off) = hi;
                            *(uint32_t*)((char*)oFl + off) = lo;
                        } else if (EPI == E_ATOMIC) {
                            atomicAdd(outF + (size_t)row * N + col, v0);
                            atomicAdd(outF + (size_t)row * N + col + 1, v1);
                        }
                    }
                }
            }
#pragma unroll
            for (int i = 0; i < 4; i++)
#pragma unroll
                for (int j = 0; j < JT; j++)
#pragma unroll
                    for (int r = 0; r < 4; r++) acc[i][j][r] = 0.f;
        }
    }
}

// ---------------- msdeform sampling (fp16 value) ----------------
__global__ void sample_kernel(const float* __restrict__ ref,
                              hf* __restrict__ ah, hf* __restrict__ al) {
    __shared__ int   s_off[8][32][4];
    __shared__ float s_w  [8][32][4];

    const int wid = threadIdx.x >> 5, lane = threadIdx.x & 31;
    const int tw = wid & 3;
    const int m = blockIdx.x * 2 + (wid >> 2);
    const int b = m / NTOK;
    const int hh = lane >> 4;
    const int head = (tw << 1) | hh;
    const int pt = lane & 15;

    float logit = g_attn[(size_t)m * 128 + head * 16 + pt];
    float mx = logit;
#pragma unroll
    for (int o = 8; o; o >>= 1) mx = fmaxf(mx, __shfl_xor_sync(0xffffffffu, mx, o, 16));
    float e = __expf(logit - mx);
    float sum = e;
#pragma unroll
    for (int o = 8; o; o >>= 1) sum += __shfl_xor_sync(0xffffffffu, sum, o, 16);
    float aw = e / sum;

    const int l = pt >> 2;
    const int Wl = c_lvl_W[l];
    float2 oxy = ((const float2*)g_off)[(size_t)m * 128 + head * 16 + pt];
    float2 rxy = ((const float2*)ref)[(size_t)m * 4 + l];
    float x = fmaf(rxy.x, (float)Wl, oxy.x) - 0.5f;
    float y = fmaf(rxy.y, (float)Wl, oxy.y) - 0.5f;
    float x0f = floorf(x), y0f = floorf(y);
    float fx = x - x0f, fy = y - y0f;
    int x0 = (int)x0f, y0 = (int)y0f;
    int x1 = x0 + 1, y1 = y0 + 1;
    bool vx0 = (x0 >= 0) & (x0 < Wl);
    bool vx1 = (x1 >= 0) & (x1 < Wl);
    bool vy0 = (y0 >= 0) & (y0 < Wl);
    bool vy1 = (y1 >= 0) & (y1 < Wl);
    int xc0 = min(max(x0, 0), Wl - 1), xc1 = min(max(x1, 0), Wl - 1);
    int yc0 = min(max(y0, 0), Wl - 1), yc1 = min(max(y1, 0), Wl - 1);
    float w00 = (vx0 & vy0) ? aw * (1.f - fx) * (1.f - fy) : 0.f;
    float w10 = (vx1 & vy0) ? aw * fx * (1.f - fy) : 0.f;
    float w01 = (vx0 & vy1) ? aw * (1.f - fx) * fy : 0.f;
    float w11 = (vx1 & vy1) ? aw * fx * fy : 0.f;
    int rowbase = b * NTOK + c_lvl_start[l];
    int hb = head * 64;
    s_off[wid][lane][0] = (rowbase + yc0 * Wl + xc0) * 512 + hb;
    s_off[wid][lane][1] = (rowbase + yc0 * Wl + xc1) * 512 + hb;
    s_off[wid][lane][2] = (rowbase + yc1 * Wl + xc0) * 512 + hb;
    s_off[wid][lane][3] = (rowbase + yc1 * Wl + xc1) * 512 + hb;
    s_w[wid][lane][0] = w00; s_w[wid][lane][1] = w10;
    s_w[wid][lane][2] = w01; s_w[wid][lane][3] = w11;
    __syncwarp();

    const int c2 = lane & 15;
    float accx = 0.f, accy = 0.f;
    const char* vb = (const char*)g_valhf + c2 * 4;
#pragma unroll
    for (int s = 0; s < 16; s++) {
        int slot = (hh << 4) | s;
        int4 io = *(const int4*)s_off[wid][slot];
        float4 wv = *(const float4*)s_w[wid][slot];
        __half2 v;
        float2 vf;
        v = *(const __half2*)(vb + io.x); vf = __half22float2(v);
        accx = fmaf(wv.x, vf.x, accx); accy = fmaf(wv.x, vf.y, accy);
        v = *(const __half2*)(vb + io.y); vf = __half22float2(v);
        accx = fmaf(wv.y, vf.x, accx); accy = fmaf(wv.y, vf.y, accy);
        v = *(const __half2*)(vb + io.z); vf = __half22float2(v);
        accx = fmaf(wv.z, vf.x, accx); accy = fmaf(wv.z, vf.y, accy);
        v = *(const __half2*)(vb + io.w); vf = __half22float2(v);
        accx = fmaf(wv.w, vf.x, accx); accy = fmaf(wv.w, vf.y, accy);
    }

    uint32_t hi, lo;
    split2(accx, accy, hi, lo);
    int k0 = head * 32 + c2 * 2;
    size_t off = blk_off(m, k0, 256);
    *(uint32_t*)((char*)ah + off) = hi;
    *(uint32_t*)((char*)al + off) = lo;
}

// ---------------- LayerNorm over D=256 ----------------
template <int MODE>
__global__ void ln_kernel(const float* __restrict__ in, const float* __restrict__ g,
                          const float* __restrict__ be, float* __restrict__ out,
                          hf* __restrict__ oh, hf* __restrict__ ol,
                          float* __restrict__ t2i, const float* __restrict__ b2) {
    int m = blockIdx.x;
    int t = threadIdx.x;
    float v = in[(size_t)m * Dd + t];
    float s = v, sq = v * v;
#pragma unroll
    for (int o = 16; o; o >>= 1) {
        s += __shfl_xor_sync(0xffffffffu, s, o);
        sq += __shfl_xor_sync(0xffffffffu, sq, o);
    }
    __shared__ float ss[8], ssq[8];
    __shared__ float s_mean, s_rstd;
    if ((t & 31) == 0) { ss[t >> 5] = s; ssq[t >> 5] = sq; }
    __syncthreads();
    if (t == 0) {
        float ts = 0.f, tsq = 0.f;
#pragma unroll
        for (int i = 0; i < 8; i++) { ts += ss[i]; tsq += ssq[i]; }
        float mean = ts * (1.f / Dd);
        float var = tsq * (1.f / Dd) - mean * mean;
        s_mean = mean;
        s_rstd = rsqrtf(var + 1e-5f);
    }
    __syncthreads();
    float o = (v - s_mean) * s_rstd * g[t] + be[t];
    out[(size_t)m * Dd + t] = o;
    if (MODE == 1) {
        hf hb, lb;
        splitf(o, hb, lb);
        size_t off = blk_off(m, t, 256);
        *(hf*)((char*)oh + off) = hb;
        *(hf*)((char*)ol + off) = lb;
        t2i[(size_t)m * Dd + t] = o + b2[t];
    }
}

// ---------------- launch ----------------
extern "C" void kernel_launch(void* const* d_in, const int* in_sizes, int n_in,
                              void* d_out, int out_size) {
    const float* src   = (const float*)d_in[0];
    const float* pos   = (const float*)d_in[1];
    const float* ref   = (const float*)d_in[2];
    const float* w_val = (const float*)d_in[3];
    const float* b_val = (const float*)d_in[4];
    const float* w_off = (const float*)d_in[5];
    const float* b_off = (const float*)d_in[6];
    const float* w_att = (const float*)d_in[7];
    const float* b_att = (const float*)d_in[8];
    const float* w_out = (const float*)d_in[9];
    const float* b_out = (const float*)d_in[10];
    const float* g1    = (const float*)d_in[11];
    const float* be1   = (const float*)d_in[12];
    const float* w1    = (const float*)d_in[13];
    const float* b1    = (const float*)d_in[14];
    const float* w2    = (const float*)d_in[15];
    const float* b2    = (const float*)d_in[16];
    const float* g2    = (const float*)d_in[17];
    const float* be2   = (const float*)d_in[18];
    const unsigned char* mask = (const unsigned char*)d_in[21];

    hf *srch, *srcl, *qh, *ql, *ah, *al, *xh, *xl, *hh, *hl, *valhf;
    hf *wv, *wc, *wo, *w1p, *w2p;
    float *p_off, *p_attn, *p_t1, *p_x, *p_t2, *p_bcomb;
    cudaGetSymbolAddress((void**)&srch, g_srch);  cudaGetSymbolAddress((void**)&srcl, g_srcl);
    cudaGetSymbolAddress((void**)&qh, g_qh);      cudaGetSymbolAddress((void**)&ql, g_ql);
    cudaGetSymbolAddress((void**)&ah, g_ah);      cudaGetSymbolAddress((void**)&al, g_al);
    cudaGetSymbolAddress((void**)&xh, g_xh);      cudaGetSymbolAddress((void**)&xl, g_xl);
    cudaGetSymbolAddress((void**)&hh, g_hh);      cudaGetSymbolAddress((void**)&hl, g_hl);
    cudaGetSymbolAddress((void**)&valhf, g_valhf);
    cudaGetSymbolAddress((void**)&wv, g_wv);
    cudaGetSymbolAddress((void**)&wc, g_wc);
    cudaGetSymbolAddress((void**)&wo, g_wo);
    cudaGetSymbolAddress((void**)&w1p, g_w1);
    cudaGetSymbolAddress((void**)&w2p, g_w2);
    cudaGetSymbolAddress((void**)&p_off, g_off);
    cudaGetSymbolAddress((void**)&p_attn, g_attn);
    cudaGetSymbolAddress((void**)&p_t1, g_t1);
    cudaGetSymbolAddress((void**)&p_x, g_x);
    cudaGetSymbolAddress((void**)&p_t2, g_t2);
    cudaGetSymbolAddress((void**)&p_bcomb, g_bcomb);

    const int M = Mrows;
    const int SM64  = 128 + NST * (2 * 8192 + 64 * 64);    // 61568
    const int SM128 = 128 + NST * (2 * 8192 + 128 * 64);   // 73856
    cudaFuncSetAttribute(tc_gemm<64,  E_MASK_F16>,  cudaFuncAttributeMaxDynamicSharedMemorySize, SM64);
    cudaFuncSetAttribute(tc_gemm<128, E_OFFATTN>,   cudaFuncAttributeMaxDynamicSharedMemorySize, SM128);
    cudaFuncSetAttribute(tc_gemm<64,  E_ADD>,       cudaFuncAttributeMaxDynamicSharedMemorySize, SM64);
    cudaFuncSetAttribute(tc_gemm<128, E_RELU_SPLIT>,cudaFuncAttributeMaxDynamicSharedMemorySize, SM128);
    cudaFuncSetAttribute(tc_gemm<128, E_ATOMIC>,    cudaFuncAttributeMaxDynamicSharedMemorySize, SM128);

    // prep
    src_q_split<<<(M * Dd / 4) / 256, 256>>>(src, pos, srch, srcl, qh, ql);
    WConvArgs wa;
    wa.s[0] = w_val; wa.h[0] = wv;  wa.n4[0] = Dd * Dd / 4;  wa.kshift[0] = 8;  wa.rowoff[0] = 0;
    wa.s[1] = w_off; wa.h[1] = wc;  wa.n4[1] = Dd * Dd / 4;  wa.kshift[1] = 8;  wa.rowoff[1] = 0;
    wa.s[2] = w_att; wa.h[2] = wc;  wa.n4[2] = 128 * Dd / 4; wa.kshift[2] = 8;  wa.rowoff[2] = 256;
    wa.s[3] = w_out; wa.h[3] = wo;  wa.n4[3] = Dd * Dd / 4;  wa.kshift[3] = 8;  wa.rowoff[3] = 0;
    wa.s[4] = w1;    wa.h[4] = w1p; wa.n4[4] = FFd * Dd / 4; wa.kshift[4] = 8;  wa.rowoff[4] = 0;
    wconv_all<<<dim3(256, 5), 256>>>(wa);
    WConvArgs wb;
    wb.s[0] = w2;    wb.h[0] = w2p; wb.n4[0] = Dd * FFd / 4; wb.kshift[0] = 10; wb.rowoff[0] = 0;
    for (int i = 1; i < 5; i++) { wb.s[i] = w2; wb.h[i] = w2p; wb.n4[i] = 0; wb.kshift[i] = 10; wb.rowoff[i] = 0; }
    wconv_all<<<dim3(256, 1), 256>>>(wb);
    pack_bias<<<1, 384>>>(b_off, b_att, p_bcomb);

    // value = mask(src @ Wv^T + b) -> fp16.  jobs: 170m x 4n
    tc_gemm<64, E_MASK_F16><<<GPERS, 256, SM64>>>(
        srch, srcl, wv, b_val, nullptr, nullptr, valhf, nullptr,
        680, 4, 1, 8, 8, Dd, nullptr, mask);
    // [off ; attn] = q @ Wc^T + b.  jobs: 170m x 3n
    tc_gemm<128, E_OFFATTN><<<GPERS, 256, SM128>>>(
        qh, ql, wc, p_bcomb, p_off, p_attn, nullptr, nullptr,
        510, 3, 1, 8, 8, 384, nullptr, nullptr);
    // msdeform -> blocked split a
    sample_kernel<<<M / 2, 256>>>(ref, ah, al);
    // t1 = src + a @ Wo^T + b.  jobs: 170m x 4n
    tc_gemm<64, E_ADD><<<GPERS, 256, SM64>>>(
        ah, al, wo, b_out, p_t1, nullptr, nullptr, nullptr,
        680, 4, 1, 8, 8, Dd, src, nullptr);
    // x = LN(t1); t2init = x + b2
    ln_kernel<1><<<M, 256>>>(p_t1, g1, be1, p_x, xh, xl, p_t2, b2);
    // h = relu(x @ W1^T + b1) -> split fp16.  jobs: 170m x 8n
    tc_gemm<128, E_RELU_SPLIT><<<GPERS, 256, SM128>>>(
        xh, xl, w1p, b1, nullptr, nullptr, hh, hl,
        1360, 8, 1, 8, 8, FFd, nullptr, nullptr);
    // t2 += h @ W2^T (NT=128, K-split x2, atomic).  jobs: 170m x 2n x 2k
    tc_gemm<128, E_ATOMIC><<<GPERS, 256, SM128>>>(
        hh, hl, w2p, nullptr, p_t2, nullptr, nullptr, nullptr,
        680, 2, 2, 16, 32, Dd, nullptr, nullptr);
    // out = LN(t2)
    ln_kernel<0><<<M, 256>>>(p_t2, g2, be2, (float*)d_out, nullptr, nullptr, nullptr, nullptr);
}

// round 9
// speedup vs baseline: 4.5080x; 1.2511x over previous
#include <cuda_runtime.h>
#include <cuda_fp16.h>
#include <math.h>
#include <stdint.h>

typedef __half hf;

// ---------------- problem constants ----------------
#define Bb 4
#define NTOK 5440
#define Mrows (Bb * NTOK)   // 21760
#define Dd 256
#define FFd 1024
#define NHh 8
#define NLl 4
#define NPp 4
#define DHh 32
#define GPERS 304

__device__ __constant__ int c_lvl_W[4]     = {64, 32, 16, 8};
__device__ __constant__ int c_lvl_start[4] = {0, 4096, 5120, 5376};

// ---------------- scratch (device globals) ----------------
__device__ hf    g_srcf[Mrows * Dd];
__device__ hf    g_qf  [Mrows * Dd];
__device__ hf    g_af  [Mrows * Dd];
__device__ hf    g_xf  [Mrows * Dd];
__device__ hf    g_hf  [Mrows * FFd];
__device__ hf    g_valhf[Mrows * Dd];          // value fp16 row-major (sampler)
__device__ float g_off  [Mrows * Dd];
__device__ float g_attn [Mrows * 128];
__device__ float g_t1   [Mrows * Dd];
__device__ float g_x    [Mrows * Dd];
__device__ float g_t2   [Mrows * Dd];
// fp16 weights, blocked layout
__device__ hf g_wv[Dd*Dd];
__device__ hf g_wc[384*Dd];
__device__ hf g_wo[Dd*Dd];
__device__ hf g_w1[FFd*Dd];
__device__ hf g_w2[Dd*FFd];

// ---------------- blocked layout ----------------
__device__ __forceinline__ size_t blk_off(int row, int k, int K) {
    uint32_t o = (uint32_t)(row & 127) * 64 + (uint32_t)(k & 31) * 2;
    o = o ^ ((o >> 3) & 0x70);
    return ((size_t)((row >> 7) * (K >> 5) + (k >> 5)) << 13) + o;
}
#define SWZ(o) ((o) ^ (((o) >> 3) & 0x70))

// ---------------- PTX helpers ----------------
__device__ __forceinline__ uint32_t smem_u32(const void* p) {
    uint32_t a;
    asm("{ .reg .u64 t; cvta.to.shared.u64 t, %1; cvt.u32.u64 %0, t; }" : "=r"(a) : "l"(p));
    return a;
}
#define MBAR_INIT(addr, cnt) \
    asm volatile("mbarrier.init.shared.b64 [%0], %1;" :: "r"((uint32_t)(addr)), "r"((uint32_t)(cnt)) : "memory")
#define MBAR_ARRIVE(addr) \
    asm volatile("mbarrier.arrive.shared.b64 _, [%0];" :: "r"((uint32_t)(addr)) : "memory")
#define MBAR_EXPECT_TX(addr, tx) \
    asm volatile("mbarrier.arrive.expect_tx.shared.b64 _, [%0], %1;" :: "r"((uint32_t)(addr)), "r"((uint32_t)(tx)) : "memory")
#define BULK_G2S(dst, src, bytes, mbar) \
    asm volatile("cp.async.bulk.shared::cluster.global.mbarrier::complete_tx::bytes [%0], [%1], %2, [%3];" \
        :: "r"((uint32_t)(dst)), "l"(src), "r"((uint32_t)(bytes)), "r"((uint32_t)(mbar)) : "memory")
#define FENCE_ASYNC() asm volatile("fence.proxy.async.shared::cta;" ::: "memory")

#define MBAR_WAIT(addr, par) do { \
    uint32_t _m = (uint32_t)(addr); uint32_t _p = (uint32_t)(par); uint32_t _d; \
    asm volatile("{\n\t.reg .pred p;\n\t" \
        "mbarrier.try_wait.parity.acquire.cta.shared::cta.b64 p, [%1], %2;\n\t" \
        "selp.b32 %0, 1, 0, p;\n\t}" : "=r"(_d) : "r"(_m), "r"(_p) : "memory"); \
    if (!_d) { \
        asm volatile("{\n\t.reg .pred P1;\n\t" \
            "WL_%=:\n\t" \
            "mbarrier.try_wait.parity.acquire.cta.shared::cta.b64 P1, [%0], %1, 0x989680;\n\t" \
            "@P1 bra.uni WD_%=;\n\t" \
            "bra.uni WL_%=;\n\t" \
            "WD_%=:\n\t}" :: "r"(_m), "r"(_p) : "memory"); \
    } } while (0)

__device__ __forceinline__ void ldsm4(uint32_t* r, uint32_t a) {
    asm volatile("ldmatrix.sync.aligned.m8n8.x4.shared.b16 {%0,%1,%2,%3}, [%4];"
        : "=r"(r[0]), "=r"(r[1]), "=r"(r[2]), "=r"(r[3]) : "r"(a));
}
__device__ __forceinline__ void mma16816(float* d, const uint32_t* a, const uint32_t* b) {
    asm volatile("mma.sync.aligned.m16n8k16.row.col.f32.f16.f16.f32 "
        "{%0,%1,%2,%3}, {%4,%5,%6,%7}, {%8,%9}, {%0,%1,%2,%3};"
        : "+f"(d[0]), "+f"(d[1]), "+f"(d[2]), "+f"(d[3])
        : "r"(a[0]), "r"(a[1]), "r"(a[2]), "r"(a[3]), "r"(b[0]), "r"(b[1]));
}

__device__ __forceinline__ uint2 conv4(float4 v) {
    __half2 a = __floats2half2_rn(v.x, v.y);
    __half2 b = __floats2half2_rn(v.z, v.w);
    uint2 r; r.x = *(uint32_t*)&a; r.y = *(uint32_t*)&b;
    return r;
}

// ---------------- prep kernels ----------------
__global__ void src_q_conv(const float* __restrict__ src, const float* __restrict__ pos,
                           hf* __restrict__ sf, hf* __restrict__ qf) {
    int i = blockIdx.x * blockDim.x + threadIdx.x;
    int e = i * 4;
    int m = e >> 8, k = e & 255;
    size_t off = blk_off(m, k, 256);
    float4 s = ((const float4*)src)[i];
    float4 p = ((const float4*)pos)[i];
    *(uint2*)((char*)sf + off) = conv4(s);
    float4 q = make_float4(s.x + p.x, s.y + p.y, s.z + p.z, s.w + p.w);
    *(uint2*)((char*)qf + off) = conv4(q);
}

struct WConvArgs {
    const float* s[6];
    hf* h[6];
    int n4[6];
    int kshift[6];
    int rowoff[6];
};
__global__ void wconv_all(WConvArgs a) {
    int seg = blockIdx.y;
    int i = blockIdx.x * blockDim.x + threadIdx.x;
    if (i >= a.n4[seg]) return;
    int ks = a.kshift[seg];
    int K = 1 << ks;
    int e = i * 4;
    int m = (e >> ks) + a.rowoff[seg];
    int k = e & (K - 1);
    size_t off = blk_off(m, k, K);
    *(uint2*)((char*)a.h[seg] + off) = conv4(((const float4*)a.s[seg])[i]);
}

// ---------------- persistent bulk-copy HMMA GEMM (single fp16 term) ----------------
#define NST 3
enum { E_MASK_F16 = 0, E_OFFATTN = 1, E_ADD = 2, E_RELU_F16 = 3, E_ATOMIC = 4 };

template <int NT, int EPI>
__global__ __launch_bounds__(256, 2)
void tc_gemm(const hf* __restrict__ A, const hf* __restrict__ B,
             const float* __restrict__ bias, const float* __restrict__ bias2,
             float* __restrict__ outF, float* __restrict__ outF2,
             hf* __restrict__ oF16,
             int NJ, int NTC, int KTC, int CHUNKS, int KCA, int N,
             const float* __restrict__ add, const unsigned char* __restrict__ mask) {
    constexpr int CPW = NT / 4;
    constexpr int PJ  = CPW / 16;
    constexpr int JT  = CPW / 8;
    constexpr int BS  = NT * 64;
    constexpr int STG = 8192 + BS;

    extern __shared__ char sm[];
    const uint32_t smb = smem_u32(sm);
    const uint32_t fullb = smb, emptyb = smb + 48;
    const uint32_t stg0 = smb + 128;

    const int tid = threadIdx.x;
    const int wid = tid >> 5, lane = tid & 31;
    const int wm = wid & 1, wn = wid >> 1;
    const int g = lane >> 2, t4 = lane & 3;

    if (tid == 0) {
#pragma unroll
        for (int s = 0; s < NST; s++) {
            MBAR_INIT(fullb + s * 16, 1);
            MBAR_INIT(emptyb + s * 16, 8);
        }
        FENCE_ASYNC();
    }
    __syncthreads();

    const int G = gridDim.x;
    const int bid = blockIdx.x;
    const int njm = (bid < NJ) ? ((NJ - bid + G - 1) / G) : 0;
    const int T = njm * CHUNKS;

    auto issue = [&](int t) {
        int jl = t / CHUNKS, c = t - jl * CHUNKS;
        int job = bid + jl * G;
        int n = job % NTC;
        int r = job / NTC;
        int kt = (KTC == 2) ? (r & 1) : 0;
        int m = (KTC == 2) ? (r >> 1) : r;
        int cg = kt * CHUNKS + c;
        int s = t % NST;
        uint32_t dst = stg0 + s * STG;
        uint32_t mb = fullb + s * 16;
        MBAR_EXPECT_TX(mb, STG);
        const char* a0 = (const char*)A + (((size_t)m * KCA + cg) << 13);
        int bn = n * NT;
        int pB = bn >> 7;
        uint32_t ho = (uint32_t)(bn & 64) << 6;
        const char* b0 = (const char*)B + (((size_t)pB * KCA + cg) << 13) + ho;
        BULK_G2S(dst,        a0, 8192, mb);
        BULK_G2S(dst + 8192, b0, BS,   mb);
    };

    if (tid == 0) {
        int pre = T < NST ? T : NST;
        for (int t = 0; t < pre; t++) issue(t);
    }

    float acc[4][JT][4];
#pragma unroll
    for (int i = 0; i < 4; i++)
#pragma unroll
        for (int j = 0; j < JT; j++)
#pragma unroll
            for (int r = 0; r < 4; r++) acc[i][j][r] = 0.f;

    const uint32_t rA = (uint32_t)(lane & 15);
    const uint32_t qA = (uint32_t)(lane >> 4) * 16;
    const uint32_t rB = (uint32_t)(((lane >> 4) & 1) * 8 + (lane & 7));
    const uint32_t qB = (uint32_t)((lane >> 3) & 1) * 16;

    int bm = 0, bn = 0;

    for (int t = 0; t < T; t++) {
        int jl = t / CHUNKS, c = t - jl * CHUNKS;
        if (c == 0) {
            int job = bid + jl * G;
            int n = job % NTC;
            int r = job / NTC;
            int m = (KTC == 2) ? (r >> 1) : r;
            bm = m * 128;
            bn = n * NT;
        }
        const int s = t % NST;
        const int u = t / NST;
        MBAR_WAIT(fullb + s * 16, u & 1);

        const uint32_t st = stg0 + s * STG;
#pragma unroll
        for (int ks = 0; ks < 2; ks++) {
            uint32_t Af[4][4], Bf[PJ][4];
#pragma unroll
            for (int i = 0; i < 4; i++) {
                uint32_t o = (wm * 64 + i * 16 + rA) * 64 + qA + ks * 32;
                o = SWZ(o);
                ldsm4(Af[i], st + o);
            }
#pragma unroll
            for (int p = 0; p < PJ; p++) {
                uint32_t o = (wn * CPW + p * 16 + rB) * 64 + qB + ks * 32;
                o = SWZ(o);
                ldsm4(Bf[p], st + 8192 + o);
            }
#pragma unroll
            for (int i = 0; i < 4; i++)
#pragma unroll
                for (int j = 0; j < JT; j++) {
                    const uint32_t* bp = &Bf[j >> 1][(j & 1) * 2];
                    mma16816(acc[i][j], Af[i], bp);
                }
        }
        __syncwarp();
        if (lane == 0) MBAR_ARRIVE(emptyb + s * 16);
        if (tid == 0 && t + NST < T) {
            MBAR_WAIT(emptyb + s * 16, u & 1);
            issue(t + NST);
        }

        if (c == CHUNKS - 1) {
#pragma unroll
            for (int i = 0; i < 4; i++) {
                int row0 = bm + wm * 64 + i * 16 + g;
#pragma unroll
                for (int j = 0; j < JT; j++) {
                    int col = bn + wn * CPW + j * 8 + 2 * t4;
                    float b0, b1;
                    if (EPI == E_ATOMIC) { b0 = 0.f; b1 = 0.f; }
                    else if (EPI == E_OFFATTN && bn == 256) {
                        b0 = bias2[col - 256]; b1 = bias2[col - 255];
                    } else {
                        b0 = bias[col]; b1 = bias[col + 1];
                    }
#pragma unroll
                    for (int half = 0; half < 2; half++) {
                        int row = row0 + half * 8;
                        float v0 = acc[i][j][half * 2 + 0] + b0;
                        float v1 = acc[i][j][half * 2 + 1] + b1;
                        if (EPI == E_MASK_F16) {
                            if (mask[row]) { v0 = 0.f; v1 = 0.f; }
                            __half2 pk = __floats2half2_rn(v0, v1);
                            *(uint32_t*)(oF16 + (size_t)row * N + col) = *(uint32_t*)&pk;
                        } else if (EPI == E_OFFATTN) {
                            if (bn == 256)
                                *(float2*)(outF2 + (size_t)row * 128 + (col - 256)) = make_float2(v0, v1);
                            else
                                *(float2*)(outF + (size_t)row * 256 + col) = make_float2(v0, v1);
                        } else if (EPI == E_ADD) {
                            float2 r2 = *(const float2*)(add + (size_t)row * N + col);
                            *(float2*)(outF + (size_t)row * N + col) = make_float2(v0 + r2.x, v1 + r2.y);
                        } else if (EPI == E_RELU_F16) {
                            v0 = fmaxf(v0, 0.f); v1 = fmaxf(v1, 0.f);
                            __half2 pk = __floats2half2_rn(v0, v1);
                            size_t off = blk_off(row, col, N);
                            *(uint32_t*)((char*)oF16 + off) = *(uint32_t*)&pk;
                        } else if (EPI == E_ATOMIC) {
                            atomicAdd(outF + (size_t)row * N + col, v0);
                            atomicAdd(outF + (size_t)row * N + col + 1, v1);
                        }
                    }
                }
            }
#pragma unroll
            for (int i = 0; i < 4; i++)
#pragma unroll
                for (int j = 0; j < JT; j++)
#pragma unroll
                    for (int r = 0; r < 4; r++) acc[i][j][r] = 0.f;
        }
    }
}

// ---------------- msdeform sampling (fp16 value) ----------------
__global__ void sample_kernel(const float* __restrict__ ref, hf* __restrict__ af) {
    __shared__ int   s_off[8][32][4];
    __shared__ float s_w  [8][32][4];

    const int wid = threadIdx.x >> 5, lane = threadIdx.x & 31;
    const int tw = wid & 3;
    const int m = blockIdx.x * 2 + (wid >> 2);
    const int b = m / NTOK;
    const int hh = lane >> 4;
    const int head = (tw << 1) | hh;
    const int pt = lane & 15;

    float logit = g_attn[(size_t)m * 128 + head * 16 + pt];
    float mx = logit;
#pragma unroll
    for (int o = 8; o; o >>= 1) mx = fmaxf(mx, __shfl_xor_sync(0xffffffffu, mx, o, 16));
    float e = __expf(logit - mx);
    float sum = e;
#pragma unroll
    for (int o = 8; o; o >>= 1) sum += __shfl_xor_sync(0xffffffffu, sum, o, 16);
    float aw = e / sum;

    const int l = pt >> 2;
    const int Wl = c_lvl_W[l];
    float2 oxy = ((const float2*)g_off)[(size_t)m * 128 + head * 16 + pt];
    float2 rxy = ((const float2*)ref)[(size_t)m * 4 + l];
    float x = fmaf(rxy.x, (float)Wl, oxy.x) - 0.5f;
    float y = fmaf(rxy.y, (float)Wl, oxy.y) - 0.5f;
    float x0f = floorf(x), y0f = floorf(y);
    float fx = x - x0f, fy = y - y0f;
    int x0 = (int)x0f, y0 = (int)y0f;
    int x1 = x0 + 1, y1 = y0 + 1;
    bool vx0 = (x0 >= 0) & (x0 < Wl);
    bool vx1 = (x1 >= 0) & (x1 < Wl);
    bool vy0 = (y0 >= 0) & (y0 < Wl);
    bool vy1 = (y1 >= 0) & (y1 < Wl);
    int xc0 = min(max(x0, 0), Wl - 1), xc1 = min(max(x1, 0), Wl - 1);
    int yc0 = min(max(y0, 0), Wl - 1), yc1 = min(max(y1, 0), Wl - 1);
    float w00 = (vx0 & vy0) ? aw * (1.f - fx) * (1.f - fy) : 0.f;
    float w10 = (vx1 & vy0) ? aw * fx * (1.f - fy) : 0.f;
    float w01 = (vx0 & vy1) ? aw * (1.f - fx) * fy : 0.f;
    float w11 = (vx1 & vy1) ? aw * fx * fy : 0.f;
    int rowbase = b * NTOK + c_lvl_start[l];
    int hb = head * 64;
    s_off[wid][lane][0] = (rowbase + yc0 * Wl + xc0) * 512 + hb;
    s_off[wid][lane][1] = (rowbase + yc0 * Wl + xc1) * 512 + hb;
    s_off[wid][lane][2] = (rowbase + yc1 * Wl + xc0) * 512 + hb;
    s_off[wid][lane][3] = (rowbase + yc1 * Wl + xc1) * 512 + hb;
    s_w[wid][lane][0] = w00; s_w[wid][lane][1] = w10;
    s_w[wid][lane][2] = w01; s_w[wid][lane][3] = w11;
    __syncwarp();

    const int c2 = lane & 15;
    float accx = 0.f, accy = 0.f;
    const char* vb = (const char*)g_valhf + c2 * 4;
#pragma unroll
    for (int s = 0; s < 16; s++) {
        int slot = (hh << 4) | s;
        int4 io = *(const int4*)s_off[wid][slot];
        float4 wv = *(const float4*)s_w[wid][slot];
        __half2 v;
        float2 vf;
        v = *(const __half2*)(vb + io.x); vf = __half22float2(v);
        accx = fmaf(wv.x, vf.x, accx); accy = fmaf(wv.x, vf.y, accy);
        v = *(const __half2*)(vb + io.y); vf = __half22float2(v);
        accx = fmaf(wv.y, vf.x, accx); accy = fmaf(wv.y, vf.y, accy);
        v = *(const __half2*)(vb + io.z); vf = __half22float2(v);
        accx = fmaf(wv.z, vf.x, accx); accy = fmaf(wv.z, vf.y, accy);
        v = *(const __half2*)(vb + io.w); vf = __half22float2(v);
        accx = fmaf(wv.w, vf.x, accx); accy = fmaf(wv.w, vf.y, accy);
    }

    __half2 pk = __floats2half2_rn(accx, accy);
    int k0 = head * 32 + c2 * 2;
    size_t off = blk_off(m, k0, 256);
    *(uint32_t*)((char*)af + off) = *(uint32_t*)&pk;
}

// ---------------- LayerNorm over D=256 ----------------
template <int MODE>
__global__ void ln_kernel(const float* __restrict__ in, const float* __restrict__ g,
                          const float* __restrict__ be, float* __restrict__ out,
                          hf* __restrict__ oh,
                          float* __restrict__ t2i, const float* __restrict__ b2) {
    int m = blockIdx.x;
    int t = threadIdx.x;
    float v = in[(size_t)m * Dd + t];
    float s = v, sq = v * v;
#pragma unroll
    for (int o = 16; o; o >>= 1) {
        s += __shfl_xor_sync(0xffffffffu, s, o);
        sq += __shfl_xor_sync(0xffffffffu, sq, o);
    }
    __shared__ float ss[8], ssq[8];
    __shared__ float s_mean, s_rstd;
    if ((t & 31) == 0) { ss[t >> 5] = s; ssq[t >> 5] = sq; }
    __syncthreads();
    if (t == 0) {
        float ts = 0.f, tsq = 0.f;
#pragma unroll
        for (int i = 0; i < 8; i++) { ts += ss[i]; tsq += ssq[i]; }
        float mean = ts * (1.f / Dd);
        float var = tsq * (1.f / Dd) - mean * mean;
        s_mean = mean;
        s_rstd = rsqrtf(var + 1e-5f);
    }
    __syncthreads();
    float o = (v - s_mean) * s_rstd * g[t] + be[t];
    out[(size_t)m * Dd + t] = o;
    if (MODE == 1) {
        size_t off = blk_off(m, t, 256);
        *(hf*)((char*)oh + off) = __float2half_rn(o);
        t2i[(size_t)m * Dd + t] = o + b2[t];
    }
}

// ---------------- launch ----------------
extern "C" void kernel_launch(void* const* d_in, const int* in_sizes, int n_in,
                              void* d_out, int out_size) {
    const float* src   = (const float*)d_in[0];
    const float* pos   = (const float*)d_in[1];
    const float* ref   = (const float*)d_in[2];
    const float* w_val = (const float*)d_in[3];
    const float* b_val = (const float*)d_in[4];
    const float* w_off = (const float*)d_in[5];
    const float* b_off = (const float*)d_in[6];
    const float* w_att = (const float*)d_in[7];
    const float* b_att = (const float*)d_in[8];
    const float* w_out = (const float*)d_in[9];
    const float* b_out = (const float*)d_in[10];
    const float* g1    = (const float*)d_in[11];
    const float* be1   = (const float*)d_in[12];
    const float* w1    = (const float*)d_in[13];
    const float* b1    = (const float*)d_in[14];
    const float* w2    = (const float*)d_in[15];
    const float* b2    = (const float*)d_in[16];
    const float* g2    = (const float*)d_in[17];
    const float* be2   = (const float*)d_in[18];
    const unsigned char* mask = (const unsigned char*)d_in[21];

    hf *srcf, *qf, *af, *xf, *hff, *valhf;
    hf *wv, *wc, *wo, *w1p, *w2p;
    float *p_off, *p_attn, *p_t1, *p_x, *p_t2;
    cudaGetSymbolAddress((void**)&srcf, g_srcf);
    cudaGetSymbolAddress((void**)&qf, g_qf);
    cudaGetSymbolAddress((void**)&af, g_af);
    cudaGetSymbolAddress((void**)&xf, g_xf);
    cudaGetSymbolAddress((void**)&hff, g_hf);
    cudaGetSymbolAddress((void**)&valhf, g_valhf);
    cudaGetSymbolAddress((void**)&wv, g_wv);
    cudaGetSymbolAddress((void**)&wc, g_wc);
    cudaGetSymbolAddress((void**)&wo, g_wo);
    cudaGetSymbolAddress((void**)&w1p, g_w1);
    cudaGetSymbolAddress((void**)&w2p, g_w2);
    cudaGetSymbolAddress((void**)&p_off, g_off);
    cudaGetSymbolAddress((void**)&p_attn, g_attn);
    cudaGetSymbolAddress((void**)&p_t1, g_t1);
    cudaGetSymbolAddress((void**)&p_x, g_x);
    cudaGetSymbolAddress((void**)&p_t2, g_t2);

    const int M = Mrows;
    const int SM64  = 128 + NST * (8192 + 64 * 64);    // 49280... (8192+4096)*3+128 = 36992
    const int SM128 = 128 + NST * (8192 + 128 * 64);   // (8192+8192)*3+128 = 49280
    cudaFuncSetAttribute(tc_gemm<64,  E_MASK_F16>, cudaFuncAttributeMaxDynamicSharedMemorySize, SM64);
    cudaFuncSetAttribute(tc_gemm<128, E_OFFATTN>,  cudaFuncAttributeMaxDynamicSharedMemorySize, SM128);
    cudaFuncSetAttribute(tc_gemm<64,  E_ADD>,      cudaFuncAttributeMaxDynamicSharedMemorySize, SM64);
    cudaFuncSetAttribute(tc_gemm<128, E_RELU_F16>, cudaFuncAttributeMaxDynamicSharedMemorySize, SM128);
    cudaFuncSetAttribute(tc_gemm<128, E_ATOMIC>,   cudaFuncAttributeMaxDynamicSharedMemorySize, SM128);

    // prep
    src_q_conv<<<(M * Dd / 4) / 256, 256>>>(src, pos, srcf, qf);
    WConvArgs wa;
    wa.s[0] = w_val; wa.h[0] = wv;  wa.n4[0] = Dd * Dd / 4;  wa.kshift[0] = 8;  wa.rowoff[0] = 0;
    wa.s[1] = w_off; wa.h[1] = wc;  wa.n4[1] = Dd * Dd / 4;  wa.kshift[1] = 8;  wa.rowoff[1] = 0;
    wa.s[2] = w_att; wa.h[2] = wc;  wa.n4[2] = 128 * Dd / 4; wa.kshift[2] = 8;  wa.rowoff[2] = 256;
    wa.s[3] = w_out; wa.h[3] = wo;  wa.n4[3] = Dd * Dd / 4;  wa.kshift[3] = 8;  wa.rowoff[3] = 0;
    wa.s[4] = w1;    wa.h[4] = w1p; wa.n4[4] = FFd * Dd / 4; wa.kshift[4] = 8;  wa.rowoff[4] = 0;
    wa.s[5] = w2;    wa.h[5] = w2p; wa.n4[5] = Dd * FFd / 4; wa.kshift[5] = 10; wa.rowoff[5] = 0;
    wconv_all<<<dim3(256, 6), 256>>>(wa);

    // value = mask(src @ Wv^T + b) -> fp16.  jobs: 170m x 4n
    tc_gemm<64, E_MASK_F16><<<GPERS, 256, SM64>>>(
        srcf, wv, b_val, nullptr, nullptr, nullptr, valhf,
        680, 4, 1, 8, 8, Dd, nullptr, mask);
    // [off ; attn] = q @ Wc^T + b.  jobs: 170m x 3n
    tc_gemm<128, E_OFFATTN><<<GPERS, 256, SM128>>>(
        qf, wc, b_off, b_att, p_off, p_attn, nullptr,
        510, 3, 1, 8, 8, 384, nullptr, nullptr);
    // msdeform -> blocked fp16 a
    sample_kernel<<<M / 2, 256>>>(ref, af);
    // t1 = src + a @ Wo^T + b.  jobs: 170m x 4n
    tc_gemm<64, E_ADD><<<GPERS, 256, SM64>>>(
        af, wo, b_out, nullptr, p_t1, nullptr, nullptr,
        680, 4, 1, 8, 8, Dd, src, nullptr);
    // x = LN(t1); t2init = x + b2
    ln_kernel<1><<<M, 256>>>(p_t1, g1, be1, p_x, xf, p_t2, b2);
    // h = relu(x @ W1^T + b1) -> fp16.  jobs: 170m x 8n
    tc_gemm<128, E_RELU_F16><<<GPERS, 256, SM128>>>(
        xf, w1p, b1, nullptr, nullptr, nullptr, hff,
        1360, 8, 1, 8, 8, FFd, nullptr, nullptr);
    // t2 += h @ W2^T (NT=128, K-split x2, atomic).  jobs: 170m x 2n x 2k
    tc_gemm<128, E_ATOMIC><<<GPERS, 256, SM128>>>(
        hff, w2p, nullptr, nullptr, p_t2, nullptr, nullptr,
        680, 2, 2, 16, 32, Dd, nullptr, nullptr);
    // out = LN(t2)
    ln_kernel<0><<<M, 256>>>(p_t2, g2, be2, (float*)d_out, nullptr, nullptr, nullptr);
}